// round 2
// baseline (speedup 1.0000x reference)
#include <cuda_runtime.h>
#include <math.h>

// ---------------------------------------------------------------------------
// Problem constants (fixed shapes)
// ---------------------------------------------------------------------------
#define Bb     2
#define Ll     2048
#define Dm     1024
#define Hh     32
#define Pp     64
#define Nn     128
#define KCONV  4
#define Ck     256
#define Nc     8          // Ll / Ck
#define Inter  2048
#define ConvD  2304
#define ProjD  4384
#define BL     (Bb * Ll)  // 4096

// ---------------------------------------------------------------------------
// Scratch (device globals; no dynamic allocation allowed)
// ---------------------------------------------------------------------------
__device__ float g_proj[(size_t)BL * ProjD];          // 71.8 MB  [bl, ProjD]
__device__ float g_conv[(size_t)BL * ConvD];          // 37.7 MB  [bl, ConvD] post conv+silu
__device__ float g_dtv[(size_t)BL * Hh];              // softplus(dt)
__device__ float g_acum[(size_t)Bb * Nc * Hh * Ck];   // per-chunk cumsum of dt*A  [bc,h,l]
__device__ float g_gm[(size_t)Bb * Nc * Ck * Ck];     // C·B^T per (b,c)  [bc,s,z]
__device__ float g_y[(size_t)BL * Inter];             // Y_diag then final Y then yn (in place)
__device__ float g_states[(size_t)Bb * Nc * Hh * Pp * Nn];
__device__ float g_prev[(size_t)Bb * Nc * Hh * Pp * Nn];

__device__ __forceinline__ float siluf(float x) { return x / (1.f + expf(-x)); }

// ---------------------------------------------------------------------------
// Generic 128x128x16 fp32 SGEMM: C[M,N] = A[M,K] * B[N,K]^T   (256 threads)
// ---------------------------------------------------------------------------
__device__ __forceinline__ void sgemm_tile(const float* __restrict__ A,
                                           const float* __restrict__ B,
                                           float* __restrict__ C,
                                           int M, int N, int K) {
    __shared__ float As[16][128];
    __shared__ float Bs[16][128];
    const int tid = threadIdx.x;
    const int m0 = blockIdx.y * 128;
    const int n0 = blockIdx.x * 128;
    const int ty = tid >> 4, tx = tid & 15;
    const int lr = tid >> 1;
    const int lc = (tid & 1) * 8;

    float acc[8][8];
#pragma unroll
    for (int i = 0; i < 8; i++)
#pragma unroll
        for (int j = 0; j < 8; j++) acc[i][j] = 0.f;

    for (int k0 = 0; k0 < K; k0 += 16) {
        float4 a0 = make_float4(0.f, 0.f, 0.f, 0.f), a1 = a0;
        if (m0 + lr < M) {
            const float* p = A + (size_t)(m0 + lr) * K + k0 + lc;
            a0 = *(const float4*)p;
            a1 = *(const float4*)(p + 4);
        }
        float4 b0 = make_float4(0.f, 0.f, 0.f, 0.f), b1 = b0;
        if (n0 + lr < N) {
            const float* p = B + (size_t)(n0 + lr) * K + k0 + lc;
            b0 = *(const float4*)p;
            b1 = *(const float4*)(p + 4);
        }
        As[lc + 0][lr] = a0.x; As[lc + 1][lr] = a0.y; As[lc + 2][lr] = a0.z; As[lc + 3][lr] = a0.w;
        As[lc + 4][lr] = a1.x; As[lc + 5][lr] = a1.y; As[lc + 6][lr] = a1.z; As[lc + 7][lr] = a1.w;
        Bs[lc + 0][lr] = b0.x; Bs[lc + 1][lr] = b0.y; Bs[lc + 2][lr] = b0.z; Bs[lc + 3][lr] = b0.w;
        Bs[lc + 4][lr] = b1.x; Bs[lc + 5][lr] = b1.y; Bs[lc + 6][lr] = b1.z; Bs[lc + 7][lr] = b1.w;
        __syncthreads();
#pragma unroll
        for (int kk = 0; kk < 16; kk++) {
            float4 ra0 = *(const float4*)&As[kk][ty * 8];
            float4 ra1 = *(const float4*)&As[kk][ty * 8 + 4];
            float4 rb0 = *(const float4*)&Bs[kk][tx * 8];
            float4 rb1 = *(const float4*)&Bs[kk][tx * 8 + 4];
            float ra[8] = {ra0.x, ra0.y, ra0.z, ra0.w, ra1.x, ra1.y, ra1.z, ra1.w};
            float rb[8] = {rb0.x, rb0.y, rb0.z, rb0.w, rb1.x, rb1.y, rb1.z, rb1.w};
#pragma unroll
            for (int i = 0; i < 8; i++)
#pragma unroll
                for (int j = 0; j < 8; j++) acc[i][j] += ra[i] * rb[j];
        }
        __syncthreads();
    }
#pragma unroll
    for (int i = 0; i < 8; i++) {
        int gm = m0 + ty * 8 + i;
        if (gm >= M) continue;
        float* pc = C + (size_t)gm * N + n0 + tx * 8;
#pragma unroll
        for (int j = 0; j < 8; j++) {
            int gn = n0 + tx * 8 + j;
            if (gn < N) pc[j] = acc[i][j];
        }
    }
}

__global__ __launch_bounds__(256) void gemm_in_proj_kernel(const float* __restrict__ x,
                                                           const float* __restrict__ w) {
    sgemm_tile(x, w, g_proj, BL, ProjD, Dm);
}

__global__ __launch_bounds__(256) void gemm_out_proj_kernel(const float* __restrict__ w,
                                                            float* __restrict__ out) {
    sgemm_tile(g_y, w, out, BL, Dm, Inter);
}

// ---------------------------------------------------------------------------
// Depthwise causal conv1d (K=4) + bias + SiLU over proj[:, Inter : Inter+ConvD]
// ---------------------------------------------------------------------------
__global__ void conv_silu_kernel(const float* __restrict__ cw, const float* __restrict__ cb) {
    int idx = blockIdx.x * blockDim.x + threadIdx.x;
    if (idx >= BL * ConvD) return;
    int ch = idx % ConvD;
    int bl = idx / ConvD;
    int l = bl % Ll;
    int blbase = bl - l;
    float acc = cb[ch];
#pragma unroll
    for (int k = 0; k < KCONV; k++) {
        int ls = l + k - (KCONV - 1);
        if (ls >= 0)
            acc += cw[ch * KCONV + k] * g_proj[(size_t)(blbase + ls) * ProjD + Inter + ch];
    }
    g_conv[idx] = siluf(acc);
}

// ---------------------------------------------------------------------------
// dt = softplus(dt_raw + dt_bias)
// ---------------------------------------------------------------------------
__global__ void dt_kernel(const float* __restrict__ dt_bias) {
    int idx = blockIdx.x * blockDim.x + threadIdx.x;
    if (idx >= BL * Hh) return;
    int h = idx % Hh;
    int bl = idx / Hh;
    float v = g_proj[(size_t)bl * ProjD + Inter + ConvD + h] + dt_bias[h];
    g_dtv[idx] = (v > 20.f) ? v : log1pf(expf(v));
}

// ---------------------------------------------------------------------------
// Per-chunk inclusive cumsum of dt * A  (block = one (b,c,h), 256 threads)
// ---------------------------------------------------------------------------
__global__ void acum_kernel(const float* __restrict__ A_log) {
    int blk = blockIdx.x;            // (b*Nc + c)*Hh + h
    int h = blk % Hh;
    int bc = blk / Hh;
    int b = bc / Nc, c = bc % Nc;
    int t = threadIdx.x;
    float A = -expf(A_log[h]);
    float v = g_dtv[(size_t)(b * Ll + c * Ck + t) * Hh + h] * A;
    __shared__ float s[Ck];
    s[t] = v;
    __syncthreads();
    for (int off = 1; off < Ck; off <<= 1) {
        float x = (t >= off) ? s[t - off] : 0.f;
        __syncthreads();
        s[t] += x;
        __syncthreads();
    }
    g_acum[(size_t)blk * Ck + t] = s[t];
}

// ---------------------------------------------------------------------------
// Gm[s,z] = sum_n C[s,n] * B[z,n]  per (b,c).  64x64 tiles, lower triangle only.
// ---------------------------------------------------------------------------
__global__ __launch_bounds__(256) void gm_kernel() {
    int bc = blockIdx.x;
    int sT = blockIdx.y, zT = blockIdx.z;
    if (zT > sT) return;
    int b = bc / Nc, c = bc % Nc;
    int rowbase = b * Ll + c * Ck;
    __shared__ float Cs[16][65];
    __shared__ float Bs[16][65];
    int tid = threadIdx.x;
    int ty = tid >> 4, tx = tid & 15;
    float acc[4][4];
#pragma unroll
    for (int i = 0; i < 4; i++)
#pragma unroll
        for (int j = 0; j < 4; j++) acc[i][j] = 0.f;

    int lrow = tid >> 2;            // 0..63
    int lcol = (tid & 3) * 4;       // 0..12

    for (int n0 = 0; n0 < Nn; n0 += 16) {
        const float* pc = g_conv + (size_t)(rowbase + sT * 64 + lrow) * ConvD + Inter + Nn + n0 + lcol;
        const float* pb = g_conv + (size_t)(rowbase + zT * 64 + lrow) * ConvD + Inter + n0 + lcol;
#pragma unroll
        for (int u = 0; u < 4; u++) Cs[lcol + u][lrow] = pc[u];
#pragma unroll
        for (int u = 0; u < 4; u++) Bs[lcol + u][lrow] = pb[u];
        __syncthreads();
#pragma unroll
        for (int kk = 0; kk < 16; kk++) {
            float rc[4], rb[4];
#pragma unroll
            for (int i = 0; i < 4; i++) rc[i] = Cs[kk][ty * 4 + i];
#pragma unroll
            for (int j = 0; j < 4; j++) rb[j] = Bs[kk][tx * 4 + j];
#pragma unroll
            for (int i = 0; i < 4; i++)
#pragma unroll
                for (int j = 0; j < 4; j++) acc[i][j] += rc[i] * rb[j];
        }
        __syncthreads();
    }
#pragma unroll
    for (int i = 0; i < 4; i++) {
        int sg = sT * 64 + ty * 4 + i;
        float* pg = g_gm + ((size_t)bc * Ck + sg) * Ck + zT * 64 + tx * 4;
#pragma unroll
        for (int j = 0; j < 4; j++) pg[j] = acc[i][j];
    }
}

// ---------------------------------------------------------------------------
// Y_diag[s,h,p] = sum_{z<=s} Gm[s,z]*exp(Acum[s]-Acum[z]) * hs[z,p]*dt[z]
// block = (b*c, h, sTile of 64).  256 threads, 4x4 micro.
// ---------------------------------------------------------------------------
__global__ __launch_bounds__(256) void ydiag_kernel() {
    int bc = blockIdx.x;
    int h = blockIdx.y;
    int sT = blockIdx.z;
    int b = bc / Nc, c = bc % Nc;
    int tid = threadIdx.x;
    int ty = tid >> 4, tx = tid & 15;

    __shared__ float Ms[64][65];
    __shared__ float Hs[64][65];
    __shared__ float sAc[64], zAc[64];

    const float* acumC = g_acum + ((size_t)bc * Hh + h) * Ck;
    if (tid < 64) sAc[tid] = acumC[sT * 64 + tid];
    int rowbase = b * Ll + c * Ck;

    float acc[4][4];
#pragma unroll
    for (int i = 0; i < 4; i++)
#pragma unroll
        for (int j = 0; j < 4; j++) acc[i][j] = 0.f;

    for (int zT = 0; zT <= sT; zT++) {
        if (tid < 64) zAc[tid] = acumC[zT * 64 + tid];
        {
            int zz = tid >> 2;
            int p0 = (tid & 3) * 16;
            int l = rowbase + zT * 64 + zz;
            float d = g_dtv[(size_t)l * Hh + h];
            const float* ph = g_conv + (size_t)l * ConvD + h * Pp + p0;
#pragma unroll
            for (int u = 0; u < 16; u++) Hs[zz][p0 + u] = ph[u] * d;
        }
        __syncthreads();
        {
            int ss4 = (tid & 15) * 4;
            int zz4 = (tid >> 4) * 4;
#pragma unroll
            for (int a = 0; a < 4; a++) {
                int zz = zz4 + a;
                float az = zAc[zz];
                int zg = zT * 64 + zz;
#pragma unroll
                for (int q = 0; q < 4; q++) {
                    int ss = ss4 + q;
                    int sg = sT * 64 + ss;
                    float m = 0.f;
                    if (zg <= sg)
                        m = g_gm[((size_t)bc * Ck + sg) * Ck + zg] * expf(sAc[ss] - az);
                    Ms[zz][ss] = m;
                }
            }
        }
        __syncthreads();
#pragma unroll 4
        for (int zz = 0; zz < 64; zz++) {
            float rm[4], rh[4];
#pragma unroll
            for (int i = 0; i < 4; i++) rm[i] = Ms[zz][ty * 4 + i];
#pragma unroll
            for (int j = 0; j < 4; j++) rh[j] = Hs[zz][tx * 4 + j];
#pragma unroll
            for (int i = 0; i < 4; i++)
#pragma unroll
                for (int j = 0; j < 4; j++) acc[i][j] += rm[i] * rh[j];
        }
        __syncthreads();
    }
#pragma unroll
    for (int i = 0; i < 4; i++) {
        int l = rowbase + sT * 64 + ty * 4 + i;
        float* py = g_y + (size_t)l * Inter + h * Pp + tx * 4;
#pragma unroll
        for (int j = 0; j < 4; j++) py[j] = acc[i][j];
    }
}

// ---------------------------------------------------------------------------
// states[h,p,n] = sum_l hs[l,p]*dt[l]*exp(Acum[last]-Acum[l]) * B[l,n]
// block = (b*c, h).  out [64 p][128 n].  256 threads, 4x8 micro.
// ---------------------------------------------------------------------------
__global__ __launch_bounds__(256) void states_kernel() {
    int bc = blockIdx.x, h = blockIdx.y;
    int b = bc / Nc, c = bc % Nc;
    int tid = threadIdx.x;
    int ty = tid >> 4, tx = tid & 15;
    __shared__ float Hd[32][65];
    __shared__ float Bsm[32][129];
    const float* acumC = g_acum + ((size_t)bc * Hh + h) * Ck;
    float aLast = acumC[Ck - 1];
    int rowbase = b * Ll + c * Ck;
    float acc[4][8];
#pragma unroll
    for (int i = 0; i < 4; i++)
#pragma unroll
        for (int j = 0; j < 8; j++) acc[i][j] = 0.f;

    for (int l0 = 0; l0 < Ck; l0 += 32) {
        {
            int ll = tid >> 3;
            int p0 = (tid & 7) * 8;
            int l = rowbase + l0 + ll;
            float w = g_dtv[(size_t)l * Hh + h] * expf(aLast - acumC[l0 + ll]);
            const float* ph = g_conv + (size_t)l * ConvD + h * Pp + p0;
#pragma unroll
            for (int u = 0; u < 8; u++) Hd[ll][p0 + u] = ph[u] * w;
        }
        {
            int ll = tid >> 3;
            int n0v = (tid & 7) * 16;
            const float* pb = g_conv + (size_t)(rowbase + l0 + ll) * ConvD + Inter + n0v;
#pragma unroll
            for (int u = 0; u < 16; u++) Bsm[ll][n0v + u] = pb[u];
        }
        __syncthreads();
#pragma unroll 4
        for (int ll = 0; ll < 32; ll++) {
            float rh[4], rb[8];
#pragma unroll
            for (int i = 0; i < 4; i++) rh[i] = Hd[ll][ty * 4 + i];
#pragma unroll
            for (int j = 0; j < 8; j++) rb[j] = Bsm[ll][tx * 8 + j];
#pragma unroll
            for (int i = 0; i < 4; i++)
#pragma unroll
                for (int j = 0; j < 8; j++) acc[i][j] += rh[i] * rb[j];
        }
        __syncthreads();
    }
    float* ps = g_states + ((size_t)bc * Hh + h) * Pp * Nn;
#pragma unroll
    for (int i = 0; i < 4; i++)
#pragma unroll
        for (int j = 0; j < 8; j++)
            ps[(ty * 4 + i) * Nn + tx * 8 + j] = acc[i][j];
}

// ---------------------------------------------------------------------------
// Inter-chunk recurrence: prev[c] = state entering chunk c.
// prev[0]=0;  prev[c] = states[c-1] + exp(Atot[c-1]) * prev[c-1]
// ---------------------------------------------------------------------------
__global__ void prev_kernel() {
    int idx = blockIdx.x * blockDim.x + threadIdx.x;
    if (idx >= Bb * Hh * Pp * Nn) return;
    int n = idx % Nn;
    int p = (idx / Nn) % Pp;
    int h = (idx / (Nn * Pp)) % Hh;
    int b = idx / (Nn * Pp * Hh);
    float r = 0.f;
    for (int c = 0; c < Nc; c++) {
        size_t off = (((size_t)(b * Nc + c) * Hh + h) * Pp + p) * Nn + n;
        g_prev[off] = r;
        float zl = g_acum[((size_t)(b * Nc + c) * Hh + h) * Ck + (Ck - 1)];
        r = g_states[off] + expf(zl) * r;
    }
}

// ---------------------------------------------------------------------------
// Y_off + combine: Y[l,h,p] = Y_diag + (sum_n C[l,n]*prev[p,n])*exp(Acum[l]) + D[h]*hs[l,p]
// block = (b*c, h, lTile).  out [64 l][64 p], K = 128.
// ---------------------------------------------------------------------------
__global__ __launch_bounds__(256) void yoff_kernel(const float* __restrict__ Dv) {
    int bc = blockIdx.x, h = blockIdx.y, lT = blockIdx.z;
    int b = bc / Nc, c = bc % Nc;
    int tid = threadIdx.x;
    int ty = tid >> 4, tx = tid & 15;
    __shared__ float Cs[16][65];  // [n][l]
    __shared__ float Ps[16][65];  // [n][p]
    __shared__ float lAc[64];
    const float* acumC = g_acum + ((size_t)bc * Hh + h) * Ck;
    if (tid < 64) lAc[tid] = acumC[lT * 64 + tid];
    int rowbase = b * Ll + c * Ck + lT * 64;
    const float* pprev = g_prev + ((size_t)bc * Hh + h) * Pp * Nn;

    float acc[4][4];
#pragma unroll
    for (int i = 0; i < 4; i++)
#pragma unroll
        for (int j = 0; j < 4; j++) acc[i][j] = 0.f;

    int lrow = tid >> 2;
    int lcol = (tid & 3) * 4;
    for (int n0 = 0; n0 < Nn; n0 += 16) {
        const float* pc = g_conv + (size_t)(rowbase + lrow) * ConvD + Inter + Nn + n0 + lcol;
#pragma unroll
        for (int u = 0; u < 4; u++) Cs[lcol + u][lrow] = pc[u];
        const float* pp = pprev + (size_t)lrow * Nn + n0 + lcol;
#pragma unroll
        for (int u = 0; u < 4; u++) Ps[lcol + u][lrow] = pp[u];
        __syncthreads();
#pragma unroll
        for (int kk = 0; kk < 16; kk++) {
            float rc[4], rp[4];
#pragma unroll
            for (int i = 0; i < 4; i++) rc[i] = Cs[kk][ty * 4 + i];
#pragma unroll
            for (int j = 0; j < 4; j++) rp[j] = Ps[kk][tx * 4 + j];
#pragma unroll
            for (int i = 0; i < 4; i++)
#pragma unroll
                for (int j = 0; j < 4; j++) acc[i][j] += rc[i] * rp[j];
        }
        __syncthreads();
    }
    float Dh = Dv[h];
#pragma unroll
    for (int i = 0; i < 4; i++) {
        int ll = ty * 4 + i;
        int l = rowbase + ll;
        float sd = expf(lAc[ll]);
        const float* ph = g_conv + (size_t)l * ConvD + h * Pp;
        float* py = g_y + (size_t)l * Inter + h * Pp;
#pragma unroll
        for (int j = 0; j < 4; j++) {
            int p = tx * 4 + j;
            py[p] = py[p] + acc[i][j] * sd + Dh * ph[p];
        }
    }
}

// ---------------------------------------------------------------------------
// Gated RMSNorm (group size = Inter, G=1), in place on g_y.
// block = one (b,l) row, 256 threads x 8 elements.
// ---------------------------------------------------------------------------
__global__ __launch_bounds__(256) void norm_kernel(const float* __restrict__ norm_w) {
    int row = blockIdx.x;
    int tid = threadIdx.x;
    const float* pg = g_proj + (size_t)row * ProjD;   // gate at cols [0, Inter)
    float* py = g_y + (size_t)row * Inter;
    float f[8];
    float ss = 0.f;
#pragma unroll
    for (int u = 0; u < 8; u++) {
        int i = tid + u * 256;
        float g = pg[i];
        float v = py[i] * siluf(g);
        f[u] = v;
        ss += v * v;
    }
    __shared__ float red[8];
    int lane = tid & 31, wid = tid >> 5;
#pragma unroll
    for (int o = 16; o > 0; o >>= 1) ss += __shfl_xor_sync(0xffffffffu, ss, o);
    if (lane == 0) red[wid] = ss;
    __syncthreads();
    if (tid == 0) {
        float t = 0.f;
#pragma unroll
        for (int i = 0; i < 8; i++) t += red[i];
        red[0] = t;
    }
    __syncthreads();
    float rs = rsqrtf(red[0] / (float)Inter + 1e-6f);
#pragma unroll
    for (int u = 0; u < 8; u++) {
        int i = tid + u * 256;
        py[i] = f[u] * rs * norm_w[i];
    }
}

// ---------------------------------------------------------------------------
// Launch
// ---------------------------------------------------------------------------
extern "C" void kernel_launch(void* const* d_in, const int* in_sizes, int n_in,
                              void* d_out, int out_size) {
    const float* x         = (const float*)d_in[0];
    const float* in_proj_w = (const float*)d_in[1];
    const float* conv_w    = (const float*)d_in[2];
    const float* conv_b    = (const float*)d_in[3];
    const float* dt_bias   = (const float*)d_in[4];
    const float* A_log     = (const float*)d_in[5];
    const float* Dv        = (const float*)d_in[6];
    const float* norm_w    = (const float*)d_in[7];
    const float* out_proj_w= (const float*)d_in[8];
    float* out = (float*)d_out;

    // 1) in-projection GEMM: [4096,1024] x [4384,1024]^T -> g_proj
    {
        dim3 grid((ProjD + 127) / 128, BL / 128);
        gemm_in_proj_kernel<<<grid, 256>>>(x, in_proj_w);
    }
    // 2) depthwise causal conv + SiLU
    {
        int total = BL * ConvD;
        conv_silu_kernel<<<(total + 255) / 256, 256>>>(conv_w, conv_b);
    }
    // 3) dt softplus
    {
        int total = BL * Hh;
        dt_kernel<<<(total + 255) / 256, 256>>>(dt_bias);
    }
    // 4) per-chunk cumsum of dt*A
    acum_kernel<<<Bb * Nc * Hh, Ck>>>(A_log);
    // 5) Gm = C B^T per (b,c), lower triangle tiles
    {
        dim3 grid(Bb * Nc, Ck / 64, Ck / 64);
        gm_kernel<<<grid, 256>>>();
    }
    // 6) intra-chunk Y_diag
    {
        dim3 grid(Bb * Nc, Hh, Ck / 64);
        ydiag_kernel<<<grid, 256>>>();
    }
    // 7) per-chunk final states
    {
        dim3 grid(Bb * Nc, Hh);
        states_kernel<<<grid, 256>>>();
    }
    // 8) inter-chunk recurrence
    {
        int total = Bb * Hh * Pp * Nn;
        prev_kernel<<<(total + 255) / 256, 256>>>();
    }
    // 9) Y_off + D residual + combine
    {
        dim3 grid(Bb * Nc, Hh, Ck / 64);
        yoff_kernel<<<grid, 256>>>(Dv);
    }
    // 10) gated RMSNorm (in place)
    norm_kernel<<<BL, 256>>>(norm_w);
    // 11) out-projection GEMM: [4096,2048] x [1024,2048]^T -> out
    {
        dim3 grid(Dm / 128, BL / 128);
        gemm_out_proj_kernel<<<grid, 256>>>(out_proj_w, out);
    }
    (void)in_sizes; (void)n_in; (void)out_size;
}

// round 3
// speedup vs baseline: 1.6334x; 1.6334x over previous
#include <cuda_runtime.h>
#include <cuda_bf16.h>
#include <math.h>

// ---------------------------------------------------------------------------
// Problem constants (fixed shapes)
// ---------------------------------------------------------------------------
#define Bb     2
#define Ll     2048
#define Dm     1024
#define Hh     32
#define Pp     64
#define Nn     128
#define KCONV  4
#define Ck     256
#define Nc     8          // Ll / Ck
#define Inter  2048
#define ConvD  2304
#define ProjD  4384
#define BL     (Bb * Ll)  // 4096

// ---------------------------------------------------------------------------
// Scratch (device globals; no dynamic allocation allowed)
// ---------------------------------------------------------------------------
__device__ float g_proj[(size_t)BL * ProjD];          // [bl, ProjD]
__device__ float g_conv[(size_t)BL * ConvD];          // [bl, ConvD] post conv+silu
__device__ float g_dtv[(size_t)BL * Hh];              // softplus(dt)
__device__ float g_acum[(size_t)Bb * Nc * Hh * Ck];   // per-chunk cumsum of dt*A
__device__ float g_gm[(size_t)Bb * Nc * Ck * Ck];     // C·B^T per (b,c)
__device__ float g_y[(size_t)BL * Inter];
__device__ float g_states[(size_t)Bb * Nc * Hh * Pp * Nn];
__device__ float g_prev[(size_t)Bb * Nc * Hh * Pp * Nn];

// bf16 split buffers for tensor-core GEMMs (sized for the larger use)
__device__ __nv_bfloat16 g_Ah[(size_t)BL * Inter];
__device__ __nv_bfloat16 g_Al[(size_t)BL * Inter];
__device__ __nv_bfloat16 g_Bh[(size_t)ProjD * Dm];
__device__ __nv_bfloat16 g_Bl[(size_t)ProjD * Dm];

__device__ __forceinline__ float siluf(float x) { return x / (1.f + expf(-x)); }

// ---------------------------------------------------------------------------
// PTX helpers
// ---------------------------------------------------------------------------
__device__ __forceinline__ unsigned su32(const void* p) {
    return (unsigned)__cvta_generic_to_shared(p);
}

__device__ __forceinline__ void cp16(unsigned dst, const void* src, bool ok) {
    int sz = ok ? 16 : 0;
    asm volatile("cp.async.cg.shared.global [%0], [%1], 16, %2;\n"
                 :: "r"(dst), "l"(src), "r"(sz));
}

__device__ __forceinline__ void ldsm4(unsigned& r0, unsigned& r1, unsigned& r2, unsigned& r3,
                                      unsigned addr) {
    asm volatile("ldmatrix.sync.aligned.m8n8.x4.shared.b16 {%0,%1,%2,%3}, [%4];"
                 : "=r"(r0), "=r"(r1), "=r"(r2), "=r"(r3) : "r"(addr));
}

__device__ __forceinline__ void mma16816(float* c, const unsigned* a, const unsigned* b) {
    asm volatile(
        "mma.sync.aligned.m16n8k16.row.col.f32.bf16.bf16.f32 "
        "{%0,%1,%2,%3}, {%4,%5,%6,%7}, {%8,%9}, {%0,%1,%2,%3};"
        : "+f"(c[0]), "+f"(c[1]), "+f"(c[2]), "+f"(c[3])
        : "r"(a[0]), "r"(a[1]), "r"(a[2]), "r"(a[3]), "r"(b[0]), "r"(b[1]));
}

// ---------------------------------------------------------------------------
// Tensor-core bf16-split GEMM: C[M,N] = A[M,K] * B[N,K]^T
// A ~ Ah+Al, B ~ Bh+Bl; C = Ah*Bh + Ah*Bl + Al*Bh (fp32 accum).
// Tile 128x128x32, 256 threads (8 warps: 2(m) x 4(n)), warp tile 64x32.
// smem per stage: Ah,Al,Bh,Bl each 128 rows x (32+8 pad) bf16 = 10240 B.
// 2 stages x 40960 B = 81920 B dynamic smem.
// ---------------------------------------------------------------------------
#define GEMM_SMEM 81920

__device__ __forceinline__ void gemm_core(const __nv_bfloat16* __restrict__ Ah,
                                          const __nv_bfloat16* __restrict__ Al,
                                          const __nv_bfloat16* __restrict__ Bh,
                                          const __nv_bfloat16* __restrict__ Bl,
                                          float* __restrict__ C,
                                          int M, int N, int K) {
    extern __shared__ char dyn[];
    const unsigned sbase = su32(dyn);
    const int tid = threadIdx.x;
    const int lane = tid & 31;
    const int warp = tid >> 5;
    const int wm = warp >> 2;   // 0..1
    const int wn = warp & 3;    // 0..3
    const int m0 = blockIdx.y * 128;
    const int n0 = blockIdx.x * 128;
    const int KB = K >> 5;

    float acc[4][4][4];
#pragma unroll
    for (int a = 0; a < 4; a++)
#pragma unroll
        for (int b = 0; b < 4; b++)
#pragma unroll
            for (int c = 0; c < 4; c++) acc[a][b][c] = 0.f;

    auto issue = [&](int kb, int st) {
#pragma unroll
        for (int i = 0; i < 8; i++) {
            int g = tid + (i << 8);          // 0..2047
            int mat = g >> 9;                // 0:Ah 1:Al 2:Bh 3:Bl
            int cidx = g & 511;
            int row = cidx >> 2;
            int ch = cidx & 3;
            const __nv_bfloat16* base = (mat == 0) ? Ah : (mat == 1) ? Al : (mat == 2) ? Bh : Bl;
            int lim = (mat < 2) ? M : N;
            int gr = ((mat < 2) ? m0 : n0) + row;
            bool ok = gr < lim;
            if (!ok) gr = lim - 1;
            const void* src = base + (size_t)gr * K + (kb << 5) + (ch << 3);
            unsigned dst = sbase + st * 40960 + mat * 10240 + row * 80 + (ch << 4);
            cp16(dst, src, ok);
        }
        asm volatile("cp.async.commit_group;\n");
    };

    issue(0, 0);
    issue(1, 1);

    const int rA = lane & 15;
    const int cA = (lane >> 4) << 3;  // 0 or 8

    for (int kb = 0; kb < KB; kb++) {
        int st = kb & 1;
        if (kb + 1 < KB) asm volatile("cp.async.wait_group 1;\n");
        else             asm volatile("cp.async.wait_group 0;\n");
        __syncthreads();
        unsigned aBase = sbase + st * 40960;
        unsigned bBase = aBase + 20480;
#pragma unroll
        for (int ks = 0; ks < 2; ks++) {
            unsigned ah[4][4], al[4][4];
#pragma unroll
            for (int mf = 0; mf < 4; mf++) {
                unsigned ra = aBase + (wm * 64 + mf * 16 + rA) * 80 + (ks * 16 + cA) * 2;
                ldsm4(ah[mf][0], ah[mf][1], ah[mf][2], ah[mf][3], ra);
                ldsm4(al[mf][0], al[mf][1], al[mf][2], al[mf][3], ra + 10240);
            }
            unsigned bh[4][2], bl[4][2];
#pragma unroll
            for (int nf2 = 0; nf2 < 2; nf2++) {
                unsigned rb = bBase + (wn * 32 + nf2 * 16 + rA) * 80 + (ks * 16 + cA) * 2;
                unsigned t0, t1, t2, t3;
                ldsm4(t0, t1, t2, t3, rb);
                bh[nf2 * 2][0] = t0; bh[nf2 * 2][1] = t2;
                bh[nf2 * 2 + 1][0] = t1; bh[nf2 * 2 + 1][1] = t3;
                ldsm4(t0, t1, t2, t3, rb + 10240);
                bl[nf2 * 2][0] = t0; bl[nf2 * 2][1] = t2;
                bl[nf2 * 2 + 1][0] = t1; bl[nf2 * 2 + 1][1] = t3;
            }
#pragma unroll
            for (int mf = 0; mf < 4; mf++)
#pragma unroll
                for (int nf = 0; nf < 4; nf++) {
                    mma16816(acc[mf][nf], ah[mf], bh[nf]);
                    mma16816(acc[mf][nf], ah[mf], bl[nf]);
                    mma16816(acc[mf][nf], al[mf], bh[nf]);
                }
        }
        __syncthreads();
        if (kb + 2 < KB) issue(kb + 2, st);
    }

    // epilogue
    int g4 = lane >> 2, t4 = lane & 3;
#pragma unroll
    for (int mf = 0; mf < 4; mf++) {
        int r0 = m0 + wm * 64 + mf * 16 + g4;
#pragma unroll
        for (int nf = 0; nf < 4; nf++) {
            int cg = n0 + wn * 32 + nf * 8 + t4 * 2;
            if (cg < N) {
                float* p0 = C + (size_t)r0 * N + cg;
                p0[0] = acc[mf][nf][0];
                p0[1] = acc[mf][nf][1];
                float* p1 = p0 + (size_t)8 * N;
                p1[0] = acc[mf][nf][2];
                p1[1] = acc[mf][nf][3];
            }
        }
    }
}

__global__ __launch_bounds__(256) void gemm_in_kernel() {
    gemm_core(g_Ah, g_Al, g_Bh, g_Bl, g_proj, BL, ProjD, Dm);
}

__global__ __launch_bounds__(256) void gemm_out_kernel(float* __restrict__ out) {
    gemm_core(g_Ah, g_Al, g_Bh, g_Bl, out, BL, Dm, Inter);
}

// ---------------------------------------------------------------------------
// bf16 split conversions
// ---------------------------------------------------------------------------
__global__ void split_x_kernel(const float* __restrict__ in, int n) {
    int i = blockIdx.x * blockDim.x + threadIdx.x;
    if (i >= n) return;
    float v = in[i];
    __nv_bfloat16 h = __float2bfloat16(v);
    g_Ah[i] = h;
    g_Al[i] = __float2bfloat16(v - __bfloat162float(h));
}

__global__ void split_w_kernel(const float* __restrict__ in, int n) {
    int i = blockIdx.x * blockDim.x + threadIdx.x;
    if (i >= n) return;
    float v = in[i];
    __nv_bfloat16 h = __float2bfloat16(v);
    g_Bh[i] = h;
    g_Bl[i] = __float2bfloat16(v - __bfloat162float(h));
}

__global__ void split_y_kernel(int n) {
    int i = blockIdx.x * blockDim.x + threadIdx.x;
    if (i >= n) return;
    float v = g_y[i];
    __nv_bfloat16 h = __float2bfloat16(v);
    g_Ah[i] = h;
    g_Al[i] = __float2bfloat16(v - __bfloat162float(h));
}

// ---------------------------------------------------------------------------
// Depthwise causal conv1d (K=4) + bias + SiLU over proj[:, Inter : Inter+ConvD]
// ---------------------------------------------------------------------------
__global__ void conv_silu_kernel(const float* __restrict__ cw, const float* __restrict__ cb) {
    int idx = blockIdx.x * blockDim.x + threadIdx.x;
    if (idx >= BL * ConvD) return;
    int ch = idx % ConvD;
    int bl = idx / ConvD;
    int l = bl % Ll;
    int blbase = bl - l;
    float acc = cb[ch];
#pragma unroll
    for (int k = 0; k < KCONV; k++) {
        int ls = l + k - (KCONV - 1);
        if (ls >= 0)
            acc += cw[ch * KCONV + k] * g_proj[(size_t)(blbase + ls) * ProjD + Inter + ch];
    }
    g_conv[idx] = siluf(acc);
}

// ---------------------------------------------------------------------------
// dt = softplus(dt_raw + dt_bias)
// ---------------------------------------------------------------------------
__global__ void dt_kernel(const float* __restrict__ dt_bias) {
    int idx = blockIdx.x * blockDim.x + threadIdx.x;
    if (idx >= BL * Hh) return;
    int h = idx % Hh;
    int bl = idx / Hh;
    float v = g_proj[(size_t)bl * ProjD + Inter + ConvD + h] + dt_bias[h];
    g_dtv[idx] = (v > 20.f) ? v : log1pf(expf(v));
}

// ---------------------------------------------------------------------------
// Per-chunk inclusive cumsum of dt * A  (block = one (b,c,h), 256 threads)
// ---------------------------------------------------------------------------
__global__ void acum_kernel(const float* __restrict__ A_log) {
    int blk = blockIdx.x;            // (b*Nc + c)*Hh + h
    int h = blk % Hh;
    int bc = blk / Hh;
    int b = bc / Nc, c = bc % Nc;
    int t = threadIdx.x;
    float A = -expf(A_log[h]);
    float v = g_dtv[(size_t)(b * Ll + c * Ck + t) * Hh + h] * A;
    __shared__ float s[Ck];
    s[t] = v;
    __syncthreads();
    for (int off = 1; off < Ck; off <<= 1) {
        float x = (t >= off) ? s[t - off] : 0.f;
        __syncthreads();
        s[t] += x;
        __syncthreads();
    }
    g_acum[(size_t)blk * Ck + t] = s[t];
}

// ---------------------------------------------------------------------------
// Gm[s,z] = sum_n C[s,n] * B[z,n]  per (b,c).  64x64 tiles, lower triangle only.
// ---------------------------------------------------------------------------
__global__ __launch_bounds__(256) void gm_kernel() {
    int bc = blockIdx.x;
    int sT = blockIdx.y, zT = blockIdx.z;
    if (zT > sT) return;
    int b = bc / Nc, c = bc % Nc;
    int rowbase = b * Ll + c * Ck;
    __shared__ float Cs[16][65];
    __shared__ float Bs[16][65];
    int tid = threadIdx.x;
    int ty = tid >> 4, tx = tid & 15;
    float acc[4][4];
#pragma unroll
    for (int i = 0; i < 4; i++)
#pragma unroll
        for (int j = 0; j < 4; j++) acc[i][j] = 0.f;

    int lrow = tid >> 2;
    int lcol = (tid & 3) * 4;

    for (int n0 = 0; n0 < Nn; n0 += 16) {
        const float* pc = g_conv + (size_t)(rowbase + sT * 64 + lrow) * ConvD + Inter + Nn + n0 + lcol;
        const float* pb = g_conv + (size_t)(rowbase + zT * 64 + lrow) * ConvD + Inter + n0 + lcol;
#pragma unroll
        for (int u = 0; u < 4; u++) Cs[lcol + u][lrow] = pc[u];
#pragma unroll
        for (int u = 0; u < 4; u++) Bs[lcol + u][lrow] = pb[u];
        __syncthreads();
#pragma unroll
        for (int kk = 0; kk < 16; kk++) {
            float rc[4], rb[4];
#pragma unroll
            for (int i = 0; i < 4; i++) rc[i] = Cs[kk][ty * 4 + i];
#pragma unroll
            for (int j = 0; j < 4; j++) rb[j] = Bs[kk][tx * 4 + j];
#pragma unroll
            for (int i = 0; i < 4; i++)
#pragma unroll
                for (int j = 0; j < 4; j++) acc[i][j] += rc[i] * rb[j];
        }
        __syncthreads();
    }
#pragma unroll
    for (int i = 0; i < 4; i++) {
        int sg = sT * 64 + ty * 4 + i;
        float* pg = g_gm + ((size_t)bc * Ck + sg) * Ck + zT * 64 + tx * 4;
#pragma unroll
        for (int j = 0; j < 4; j++) pg[j] = acc[i][j];
    }
}

// ---------------------------------------------------------------------------
// Y_diag[s,h,p] = sum_{z<=s} Gm[s,z]*exp(Acum[s]-Acum[z]) * hs[z,p]*dt[z]
// ---------------------------------------------------------------------------
__global__ __launch_bounds__(256) void ydiag_kernel() {
    int bc = blockIdx.x;
    int h = blockIdx.y;
    int sT = blockIdx.z;
    int b = bc / Nc, c = bc % Nc;
    int tid = threadIdx.x;
    int ty = tid >> 4, tx = tid & 15;

    __shared__ float Ms[64][65];
    __shared__ float Hs[64][65];
    __shared__ float sAc[64], zAc[64];

    const float* acumC = g_acum + ((size_t)bc * Hh + h) * Ck;
    if (tid < 64) sAc[tid] = acumC[sT * 64 + tid];
    int rowbase = b * Ll + c * Ck;

    float acc[4][4];
#pragma unroll
    for (int i = 0; i < 4; i++)
#pragma unroll
        for (int j = 0; j < 4; j++) acc[i][j] = 0.f;

    for (int zT = 0; zT <= sT; zT++) {
        if (tid < 64) zAc[tid] = acumC[zT * 64 + tid];
        {
            int zz = tid >> 2;
            int p0 = (tid & 3) * 16;
            int l = rowbase + zT * 64 + zz;
            float d = g_dtv[(size_t)l * Hh + h];
            const float* ph = g_conv + (size_t)l * ConvD + h * Pp + p0;
#pragma unroll
            for (int u = 0; u < 16; u++) Hs[zz][p0 + u] = ph[u] * d;
        }
        __syncthreads();
        {
            int ss4 = (tid & 15) * 4;
            int zz4 = (tid >> 4) * 4;
#pragma unroll
            for (int a = 0; a < 4; a++) {
                int zz = zz4 + a;
                float az = zAc[zz];
                int zg = zT * 64 + zz;
#pragma unroll
                for (int q = 0; q < 4; q++) {
                    int ss = ss4 + q;
                    int sg = sT * 64 + ss;
                    float m = 0.f;
                    if (zg <= sg)
                        m = g_gm[((size_t)bc * Ck + sg) * Ck + zg] * expf(sAc[ss] - az);
                    Ms[zz][ss] = m;
                }
            }
        }
        __syncthreads();
#pragma unroll 4
        for (int zz = 0; zz < 64; zz++) {
            float rm[4], rh[4];
#pragma unroll
            for (int i = 0; i < 4; i++) rm[i] = Ms[zz][ty * 4 + i];
#pragma unroll
            for (int j = 0; j < 4; j++) rh[j] = Hs[zz][tx * 4 + j];
#pragma unroll
            for (int i = 0; i < 4; i++)
#pragma unroll
                for (int j = 0; j < 4; j++) acc[i][j] += rm[i] * rh[j];
        }
        __syncthreads();
    }
#pragma unroll
    for (int i = 0; i < 4; i++) {
        int l = rowbase + sT * 64 + ty * 4 + i;
        float* py = g_y + (size_t)l * Inter + h * Pp + tx * 4;
#pragma unroll
        for (int j = 0; j < 4; j++) py[j] = acc[i][j];
    }
}

// ---------------------------------------------------------------------------
// states[h,p,n] = sum_l hs[l,p]*dt[l]*exp(Acum[last]-Acum[l]) * B[l,n]
// ---------------------------------------------------------------------------
__global__ __launch_bounds__(256) void states_kernel() {
    int bc = blockIdx.x, h = blockIdx.y;
    int b = bc / Nc, c = bc % Nc;
    int tid = threadIdx.x;
    int ty = tid >> 4, tx = tid & 15;
    __shared__ float Hd[32][65];
    __shared__ float Bsm[32][129];
    const float* acumC = g_acum + ((size_t)bc * Hh + h) * Ck;
    float aLast = acumC[Ck - 1];
    int rowbase = b * Ll + c * Ck;
    float acc[4][8];
#pragma unroll
    for (int i = 0; i < 4; i++)
#pragma unroll
        for (int j = 0; j < 8; j++) acc[i][j] = 0.f;

    for (int l0 = 0; l0 < Ck; l0 += 32) {
        {
            int ll = tid >> 3;
            int p0 = (tid & 7) * 8;
            int l = rowbase + l0 + ll;
            float w = g_dtv[(size_t)l * Hh + h] * expf(aLast - acumC[l0 + ll]);
            const float* ph = g_conv + (size_t)l * ConvD + h * Pp + p0;
#pragma unroll
            for (int u = 0; u < 8; u++) Hd[ll][p0 + u] = ph[u] * w;
        }
        {
            int ll = tid >> 3;
            int n0v = (tid & 7) * 16;
            const float* pb = g_conv + (size_t)(rowbase + l0 + ll) * ConvD + Inter + n0v;
#pragma unroll
            for (int u = 0; u < 16; u++) Bsm[ll][n0v + u] = pb[u];
        }
        __syncthreads();
#pragma unroll 4
        for (int ll = 0; ll < 32; ll++) {
            float rh[4], rb[8];
#pragma unroll
            for (int i = 0; i < 4; i++) rh[i] = Hd[ll][ty * 4 + i];
#pragma unroll
            for (int j = 0; j < 8; j++) rb[j] = Bsm[ll][tx * 8 + j];
#pragma unroll
            for (int i = 0; i < 4; i++)
#pragma unroll
                for (int j = 0; j < 8; j++) acc[i][j] += rh[i] * rb[j];
        }
        __syncthreads();
    }
    float* ps = g_states + ((size_t)bc * Hh + h) * Pp * Nn;
#pragma unroll
    for (int i = 0; i < 4; i++)
#pragma unroll
        for (int j = 0; j < 8; j++)
            ps[(ty * 4 + i) * Nn + tx * 8 + j] = acc[i][j];
}

// ---------------------------------------------------------------------------
// Inter-chunk recurrence
// ---------------------------------------------------------------------------
__global__ void prev_kernel() {
    int idx = blockIdx.x * blockDim.x + threadIdx.x;
    if (idx >= Bb * Hh * Pp * Nn) return;
    int n = idx % Nn;
    int p = (idx / Nn) % Pp;
    int h = (idx / (Nn * Pp)) % Hh;
    int b = idx / (Nn * Pp * Hh);
    float r = 0.f;
    for (int c = 0; c < Nc; c++) {
        size_t off = (((size_t)(b * Nc + c) * Hh + h) * Pp + p) * Nn + n;
        g_prev[off] = r;
        float zl = g_acum[((size_t)(b * Nc + c) * Hh + h) * Ck + (Ck - 1)];
        r = g_states[off] + expf(zl) * r;
    }
}

// ---------------------------------------------------------------------------
// Y_off + combine
// ---------------------------------------------------------------------------
__global__ __launch_bounds__(256) void yoff_kernel(const float* __restrict__ Dv) {
    int bc = blockIdx.x, h = blockIdx.y, lT = blockIdx.z;
    int b = bc / Nc, c = bc % Nc;
    int tid = threadIdx.x;
    int ty = tid >> 4, tx = tid & 15;
    __shared__ float Cs[16][65];
    __shared__ float Ps[16][65];
    __shared__ float lAc[64];
    const float* acumC = g_acum + ((size_t)bc * Hh + h) * Ck;
    if (tid < 64) lAc[tid] = acumC[lT * 64 + tid];
    int rowbase = b * Ll + c * Ck + lT * 64;
    const float* pprev = g_prev + ((size_t)bc * Hh + h) * Pp * Nn;

    float acc[4][4];
#pragma unroll
    for (int i = 0; i < 4; i++)
#pragma unroll
        for (int j = 0; j < 4; j++) acc[i][j] = 0.f;

    int lrow = tid >> 2;
    int lcol = (tid & 3) * 4;
    for (int n0 = 0; n0 < Nn; n0 += 16) {
        const float* pc = g_conv + (size_t)(rowbase + lrow) * ConvD + Inter + Nn + n0 + lcol;
#pragma unroll
        for (int u = 0; u < 4; u++) Cs[lcol + u][lrow] = pc[u];
        const float* pp = pprev + (size_t)lrow * Nn + n0 + lcol;
#pragma unroll
        for (int u = 0; u < 4; u++) Ps[lcol + u][lrow] = pp[u];
        __syncthreads();
#pragma unroll
        for (int kk = 0; kk < 16; kk++) {
            float rc[4], rp[4];
#pragma unroll
            for (int i = 0; i < 4; i++) rc[i] = Cs[kk][ty * 4 + i];
#pragma unroll
            for (int j = 0; j < 4; j++) rp[j] = Ps[kk][tx * 4 + j];
#pragma unroll
            for (int i = 0; i < 4; i++)
#pragma unroll
                for (int j = 0; j < 4; j++) acc[i][j] += rc[i] * rp[j];
        }
        __syncthreads();
    }
    float Dh = Dv[h];
#pragma unroll
    for (int i = 0; i < 4; i++) {
        int ll = ty * 4 + i;
        int l = rowbase + ll;
        float sd = expf(lAc[ll]);
        const float* ph = g_conv + (size_t)l * ConvD + h * Pp;
        float* py = g_y + (size_t)l * Inter + h * Pp;
#pragma unroll
        for (int j = 0; j < 4; j++) {
            int p = tx * 4 + j;
            py[p] = py[p] + acc[i][j] * sd + Dh * ph[p];
        }
    }
}

// ---------------------------------------------------------------------------
// Gated RMSNorm (group size = Inter, G=1), in place on g_y.
// ---------------------------------------------------------------------------
__global__ __launch_bounds__(256) void norm_kernel(const float* __restrict__ norm_w) {
    int row = blockIdx.x;
    int tid = threadIdx.x;
    const float* pg = g_proj + (size_t)row * ProjD;
    float* py = g_y + (size_t)row * Inter;
    float f[8];
    float ss = 0.f;
#pragma unroll
    for (int u = 0; u < 8; u++) {
        int i = tid + u * 256;
        float g = pg[i];
        float v = py[i] * siluf(g);
        f[u] = v;
        ss += v * v;
    }
    __shared__ float red[8];
    int lane = tid & 31, wid = tid >> 5;
#pragma unroll
    for (int o = 16; o > 0; o >>= 1) ss += __shfl_xor_sync(0xffffffffu, ss, o);
    if (lane == 0) red[wid] = ss;
    __syncthreads();
    if (tid == 0) {
        float t = 0.f;
#pragma unroll
        for (int i = 0; i < 8; i++) t += red[i];
        red[0] = t;
    }
    __syncthreads();
    float rs = rsqrtf(red[0] / (float)Inter + 1e-6f);
#pragma unroll
    for (int u = 0; u < 8; u++) {
        int i = tid + u * 256;
        py[i] = f[u] * rs * norm_w[i];
    }
}

// ---------------------------------------------------------------------------
// Launch
// ---------------------------------------------------------------------------
extern "C" void kernel_launch(void* const* d_in, const int* in_sizes, int n_in,
                              void* d_out, int out_size) {
    const float* x         = (const float*)d_in[0];
    const float* in_proj_w = (const float*)d_in[1];
    const float* conv_w    = (const float*)d_in[2];
    const float* conv_b    = (const float*)d_in[3];
    const float* dt_bias   = (const float*)d_in[4];
    const float* A_log     = (const float*)d_in[5];
    const float* Dv        = (const float*)d_in[6];
    const float* norm_w    = (const float*)d_in[7];
    const float* out_proj_w= (const float*)d_in[8];
    float* out = (float*)d_out;

    cudaFuncSetAttribute(gemm_in_kernel, cudaFuncAttributeMaxDynamicSharedMemorySize, GEMM_SMEM);
    cudaFuncSetAttribute(gemm_out_kernel, cudaFuncAttributeMaxDynamicSharedMemorySize, GEMM_SMEM);

    // 1) split x and in_proj_w to bf16 hi/lo
    {
        int n = BL * Dm;
        split_x_kernel<<<(n + 255) / 256, 256>>>(x, n);
        n = ProjD * Dm;
        split_w_kernel<<<(n + 255) / 256, 256>>>(in_proj_w, n);
    }
    // 2) in-projection GEMM (tensor cores): [4096,1024] x [4384,1024]^T -> g_proj
    {
        dim3 grid((ProjD + 127) / 128, BL / 128);
        gemm_in_kernel<<<grid, 256, GEMM_SMEM>>>();
    }
    // 3) depthwise causal conv + SiLU
    {
        int total = BL * ConvD;
        conv_silu_kernel<<<(total + 255) / 256, 256>>>(conv_w, conv_b);
    }
    // 4) dt softplus
    {
        int total = BL * Hh;
        dt_kernel<<<(total + 255) / 256, 256>>>(dt_bias);
    }
    // 5) per-chunk cumsum of dt*A
    acum_kernel<<<Bb * Nc * Hh, Ck>>>(A_log);
    // 6) Gm = C B^T per (b,c)
    {
        dim3 grid(Bb * Nc, Ck / 64, Ck / 64);
        gm_kernel<<<grid, 256>>>();
    }
    // 7) intra-chunk Y_diag
    {
        dim3 grid(Bb * Nc, Hh, Ck / 64);
        ydiag_kernel<<<grid, 256>>>();
    }
    // 8) per-chunk final states
    {
        dim3 grid(Bb * Nc, Hh);
        states_kernel<<<grid, 256>>>();
    }
    // 9) inter-chunk recurrence
    {
        int total = Bb * Hh * Pp * Nn;
        prev_kernel<<<(total + 255) / 256, 256>>>();
    }
    // 10) Y_off + D residual + combine
    {
        dim3 grid(Bb * Nc, Hh, Ck / 64);
        yoff_kernel<<<grid, 256>>>(Dv);
    }
    // 11) gated RMSNorm (in place)
    norm_kernel<<<BL, 256>>>(norm_w);
    // 12) split y and out_proj_w to bf16 hi/lo
    {
        int n = BL * Inter;
        split_y_kernel<<<(n + 255) / 256, 256>>>(n);
        n = Dm * Inter;
        split_w_kernel<<<(n + 255) / 256, 256>>>(out_proj_w, n);
    }
    // 13) out-projection GEMM (tensor cores): [4096,2048] x [1024,2048]^T -> out
    {
        dim3 grid(Dm / 128, BL / 128);
        gemm_out_kernel<<<grid, 256, GEMM_SMEM>>>(out);
    }
    (void)in_sizes; (void)n_in; (void)out_size;
}

// round 5
// speedup vs baseline: 1.6357x; 1.0014x over previous
#include <cuda_runtime.h>
#include <cuda_bf16.h>
#include <math.h>
#include <stdint.h>

// ---------------------------------------------------------------------------
// Problem constants (fixed shapes)
// ---------------------------------------------------------------------------
#define Bb     2
#define Ll     2048
#define Dm     1024
#define Hh     32
#define Pp     64
#define Nn     128
#define KCONV  4
#define Ck     256
#define Nc     8          // Ll / Ck
#define Inter  2048
#define ConvD  2304
#define ProjD  4384
#define BL     (Bb * Ll)  // 4096

// ---------------------------------------------------------------------------
// Scratch (device globals; no dynamic allocation allowed)
// ---------------------------------------------------------------------------
__device__ float g_proj[(size_t)BL * ProjD];
__device__ float g_conv[(size_t)BL * ConvD];
__device__ float g_dtv[(size_t)BL * Hh];
__device__ float g_acum[(size_t)Bb * Nc * Hh * Ck];
__device__ float g_gm[(size_t)Bb * Nc * Ck * Ck];
__device__ float g_y[(size_t)BL * Inter];
__device__ float g_states[(size_t)Bb * Nc * Hh * Pp * Nn];
__device__ float g_prev[(size_t)Bb * Nc * Hh * Pp * Nn];

// bf16 split buffers
__device__ __nv_bfloat16 g_Ah[(size_t)BL * Inter];
__device__ __nv_bfloat16 g_Al[(size_t)BL * Inter];
__device__ __nv_bfloat16 g_Bh[(size_t)ProjD * Dm];
__device__ __nv_bfloat16 g_Bl[(size_t)ProjD * Dm];

__device__ __forceinline__ float siluf(float x) { return x / (1.f + expf(-x)); }

// ---------------------------------------------------------------------------
// PTX helpers
// ---------------------------------------------------------------------------
__device__ __forceinline__ unsigned su32(const void* p) {
    return (unsigned)__cvta_generic_to_shared(p);
}

__device__ __forceinline__ void cp16(unsigned dst, const void* src, bool ok) {
    int sz = ok ? 16 : 0;
    asm volatile("cp.async.cg.shared.global [%0], [%1], 16, %2;\n"
                 :: "r"(dst), "l"(src), "r"(sz));
}

__device__ __forceinline__ void ldsm4(unsigned& r0, unsigned& r1, unsigned& r2, unsigned& r3,
                                      unsigned addr) {
    asm volatile("ldmatrix.sync.aligned.m8n8.x4.shared.b16 {%0,%1,%2,%3}, [%4];"
                 : "=r"(r0), "=r"(r1), "=r"(r2), "=r"(r3) : "r"(addr));
}

__device__ __forceinline__ void mma16816(float* c, const unsigned* a, const unsigned* b) {
    asm volatile(
        "mma.sync.aligned.m16n8k16.row.col.f32.bf16.bf16.f32 "
        "{%0,%1,%2,%3}, {%4,%5,%6,%7}, {%8,%9}, {%0,%1,%2,%3};"
        : "+f"(c[0]), "+f"(c[1]), "+f"(c[2]), "+f"(c[3])
        : "r"(a[0]), "r"(a[1]), "r"(a[2]), "r"(a[3]), "r"(b[0]), "r"(b[1]));
}

// ---------------------------------------------------------------------------
// Tensor-core bf16-split GEMM: C[M,N] = A[M,K] * B[N,K]^T
// 3-pass split: C = Ah*Bh + Ah*Bl + Al*Bh (fp32 accum).
// Tile 128x128x64, 256 threads (8 warps: 2(m) x 4(n)), warp tile 64x32.
// smem row = 64 bf16 = 128 B + 16 pad = 144 B. Stage = 4 mats x 128 rows x 144 B
// = 73728 B; 2 stages = 147456 B dynamic smem.
// Register-fragment double buffering across the 4 k-steps of each chunk.
// ---------------------------------------------------------------------------
#define GEMM_SMEM (2 * 73728)

struct Frags {
    unsigned ah[4][4], al[4][4];
    unsigned bh[4][2], bl[4][2];
};

__device__ __forceinline__ void load_frags(Frags& F, unsigned stg, int ks,
                                           int wm, int wn, int lane) {
    const int rA = lane & 15;
    const int cB = ((lane >> 4) << 4);           // 0 or 16 bytes
    const unsigned colb = (unsigned)(ks * 32 + cB);
#pragma unroll
    for (int mf = 0; mf < 4; mf++) {
        unsigned ra = stg + (wm * 64 + mf * 16 + rA) * 144 + colb;
        ldsm4(F.ah[mf][0], F.ah[mf][1], F.ah[mf][2], F.ah[mf][3], ra);
        ldsm4(F.al[mf][0], F.al[mf][1], F.al[mf][2], F.al[mf][3], ra + 18432);
    }
#pragma unroll
    for (int nf2 = 0; nf2 < 2; nf2++) {
        unsigned rb = stg + 36864 + (wn * 32 + nf2 * 16 + rA) * 144 + colb;
        unsigned t0, t1, t2, t3;
        ldsm4(t0, t1, t2, t3, rb);
        F.bh[nf2 * 2][0] = t0; F.bh[nf2 * 2][1] = t2;
        F.bh[nf2 * 2 + 1][0] = t1; F.bh[nf2 * 2 + 1][1] = t3;
        ldsm4(t0, t1, t2, t3, rb + 18432);
        F.bl[nf2 * 2][0] = t0; F.bl[nf2 * 2][1] = t2;
        F.bl[nf2 * 2 + 1][0] = t1; F.bl[nf2 * 2 + 1][1] = t3;
    }
}

__device__ __forceinline__ void gemm_core(const __nv_bfloat16* __restrict__ Ah,
                                          const __nv_bfloat16* __restrict__ Al,
                                          const __nv_bfloat16* __restrict__ Bh,
                                          const __nv_bfloat16* __restrict__ Bl,
                                          float* __restrict__ C,
                                          int M, int N, int K) {
    extern __shared__ char dyn[];
    const unsigned sbase = su32(dyn);
    const int tid = threadIdx.x;
    const int lane = tid & 31;
    const int warp = tid >> 5;
    const int wm = warp >> 2;   // 0..1
    const int wn = warp & 3;    // 0..3
    const int m0 = blockIdx.y * 128;
    const int n0 = blockIdx.x * 128;
    const int KB = K >> 6;

    float acc[4][4][4];
#pragma unroll
    for (int a = 0; a < 4; a++)
#pragma unroll
        for (int b = 0; b < 4; b++)
#pragma unroll
            for (int c = 0; c < 4; c++) acc[a][b][c] = 0.f;

    auto issue = [&](int kc, int st) {
        unsigned stg = sbase + st * 73728;
#pragma unroll
        for (int i = 0; i < 16; i++) {
            int q = tid + (i << 8);           // 0..4095
            int mat = q >> 10;                // 0:Ah 1:Al 2:Bh 3:Bl
            int r = (q >> 3) & 127;
            int c16 = q & 7;
            const __nv_bfloat16* base = (mat == 0) ? Ah : (mat == 1) ? Al : (mat == 2) ? Bh : Bl;
            int gr = ((mat < 2) ? m0 : n0) + r;
            bool ok = gr < ((mat < 2) ? M : N);
            if (!ok) gr = ((mat < 2) ? M : N) - 1;
            const void* src = base + (size_t)gr * K + (kc << 6) + (c16 << 3);
            unsigned dst = stg + mat * 18432 + r * 144 + (c16 << 4);
            cp16(dst, src, ok);
        }
        asm volatile("cp.async.commit_group;\n");
    };

    issue(0, 0);
    if (KB > 1) issue(1, 1);

    Frags F[2];

    for (int kb = 0; kb < KB; kb++) {
        int st = kb & 1;
        if (kb + 1 < KB) asm volatile("cp.async.wait_group 1;\n");
        else             asm volatile("cp.async.wait_group 0;\n");
        __syncthreads();
        unsigned stg = sbase + st * 73728;

        load_frags(F[0], stg, 0, wm, wn, lane);
#pragma unroll
        for (int ks = 0; ks < 4; ks++) {
            if (ks < 3) load_frags(F[(ks + 1) & 1], stg, ks + 1, wm, wn, lane);
            Frags& f = F[ks & 1];
#pragma unroll
            for (int mf = 0; mf < 4; mf++)
#pragma unroll
                for (int nf = 0; nf < 4; nf++) {
                    mma16816(acc[mf][nf], f.ah[mf], f.bh[nf]);
                    mma16816(acc[mf][nf], f.ah[mf], f.bl[nf]);
                    mma16816(acc[mf][nf], f.al[mf], f.bh[nf]);
                }
        }
        __syncthreads();
        if (kb + 2 < KB) issue(kb + 2, st);
    }

    // epilogue
    int g4 = lane >> 2, t4 = lane & 3;
#pragma unroll
    for (int mf = 0; mf < 4; mf++) {
        int r0 = m0 + wm * 64 + mf * 16 + g4;
#pragma unroll
        for (int nf = 0; nf < 4; nf++) {
            int cg = n0 + wn * 32 + nf * 8 + t4 * 2;
            if (cg < N) {
                float* p0 = C + (size_t)r0 * N + cg;
                p0[0] = acc[mf][nf][0];
                p0[1] = acc[mf][nf][1];
                float* p1 = p0 + (size_t)8 * N;
                p1[0] = acc[mf][nf][2];
                p1[1] = acc[mf][nf][3];
            }
        }
    }
}

__global__ __launch_bounds__(256) void gemm_in_kernel() {
    gemm_core(g_Ah, g_Al, g_Bh, g_Bl, g_proj, BL, ProjD, Dm);
}

__global__ __launch_bounds__(256) void gemm_out_kernel(float* __restrict__ out) {
    gemm_core(g_Ah, g_Al, g_Bh, g_Bl, out, BL, Dm, Inter);
}

// ---------------------------------------------------------------------------
// bf16 split conversions
// ---------------------------------------------------------------------------
__global__ void split_x_kernel(const float* __restrict__ in, int n) {
    int i = blockIdx.x * blockDim.x + threadIdx.x;
    if (i >= n) return;
    float v = in[i];
    __nv_bfloat16 h = __float2bfloat16(v);
    g_Ah[i] = h;
    g_Al[i] = __float2bfloat16(v - __bfloat162float(h));
}

__global__ void split_w_kernel(const float* __restrict__ in, int n) {
    int i = blockIdx.x * blockDim.x + threadIdx.x;
    if (i >= n) return;
    float v = in[i];
    __nv_bfloat16 h = __float2bfloat16(v);
    g_Bh[i] = h;
    g_Bl[i] = __float2bfloat16(v - __bfloat162float(h));
}

// ---------------------------------------------------------------------------
// Depthwise causal conv1d (K=4) + bias + SiLU
// ---------------------------------------------------------------------------
__global__ void conv_silu_kernel(const float* __restrict__ cw, const float* __restrict__ cb) {
    int idx = blockIdx.x * blockDim.x + threadIdx.x;
    if (idx >= BL * ConvD) return;
    int ch = idx % ConvD;
    int bl = idx / ConvD;
    int l = bl % Ll;
    int blbase = bl - l;
    float acc = cb[ch];
#pragma unroll
    for (int k = 0; k < KCONV; k++) {
        int ls = l + k - (KCONV - 1);
        if (ls >= 0)
            acc += cw[ch * KCONV + k] * g_proj[(size_t)(blbase + ls) * ProjD + Inter + ch];
    }
    g_conv[idx] = siluf(acc);
}

// ---------------------------------------------------------------------------
// dt = softplus(dt_raw + dt_bias)
// ---------------------------------------------------------------------------
__global__ void dt_kernel(const float* __restrict__ dt_bias) {
    int idx = blockIdx.x * blockDim.x + threadIdx.x;
    if (idx >= BL * Hh) return;
    int h = idx % Hh;
    int bl = idx / Hh;
    float v = g_proj[(size_t)bl * ProjD + Inter + ConvD + h] + dt_bias[h];
    g_dtv[idx] = (v > 20.f) ? v : log1pf(expf(v));
}

// ---------------------------------------------------------------------------
// Per-chunk inclusive cumsum of dt * A
// ---------------------------------------------------------------------------
__global__ void acum_kernel(const float* __restrict__ A_log) {
    int blk = blockIdx.x;
    int h = blk % Hh;
    int bc = blk / Hh;
    int b = bc / Nc, c = bc % Nc;
    int t = threadIdx.x;
    float A = -expf(A_log[h]);
    float v = g_dtv[(size_t)(b * Ll + c * Ck + t) * Hh + h] * A;
    __shared__ float s[Ck];
    s[t] = v;
    __syncthreads();
    for (int off = 1; off < Ck; off <<= 1) {
        float x = (t >= off) ? s[t - off] : 0.f;
        __syncthreads();
        s[t] += x;
        __syncthreads();
    }
    g_acum[(size_t)blk * Ck + t] = s[t];
}

// ---------------------------------------------------------------------------
// Gm[s,z] = sum_n C[s,n] * B[z,n] per (b,c), lower triangle tiles
// ---------------------------------------------------------------------------
__global__ __launch_bounds__(256) void gm_kernel() {
    int bc = blockIdx.x;
    int sT = blockIdx.y, zT = blockIdx.z;
    if (zT > sT) return;
    int b = bc / Nc, c = bc % Nc;
    int rowbase = b * Ll + c * Ck;
    __shared__ float Cs[16][65];
    __shared__ float Bs[16][65];
    int tid = threadIdx.x;
    int ty = tid >> 4, tx = tid & 15;
    float acc[4][4];
#pragma unroll
    for (int i = 0; i < 4; i++)
#pragma unroll
        for (int j = 0; j < 4; j++) acc[i][j] = 0.f;

    int lrow = tid >> 2;
    int lcol = (tid & 3) * 4;

    for (int n0 = 0; n0 < Nn; n0 += 16) {
        const float* pc = g_conv + (size_t)(rowbase + sT * 64 + lrow) * ConvD + Inter + Nn + n0 + lcol;
        const float* pb = g_conv + (size_t)(rowbase + zT * 64 + lrow) * ConvD + Inter + n0 + lcol;
#pragma unroll
        for (int u = 0; u < 4; u++) Cs[lcol + u][lrow] = pc[u];
#pragma unroll
        for (int u = 0; u < 4; u++) Bs[lcol + u][lrow] = pb[u];
        __syncthreads();
#pragma unroll
        for (int kk = 0; kk < 16; kk++) {
            float rc[4], rb[4];
#pragma unroll
            for (int i = 0; i < 4; i++) rc[i] = Cs[kk][ty * 4 + i];
#pragma unroll
            for (int j = 0; j < 4; j++) rb[j] = Bs[kk][tx * 4 + j];
#pragma unroll
            for (int i = 0; i < 4; i++)
#pragma unroll
                for (int j = 0; j < 4; j++) acc[i][j] += rc[i] * rb[j];
        }
        __syncthreads();
    }
#pragma unroll
    for (int i = 0; i < 4; i++) {
        int sg = sT * 64 + ty * 4 + i;
        float* pg = g_gm + ((size_t)bc * Ck + sg) * Ck + zT * 64 + tx * 4;
#pragma unroll
        for (int j = 0; j < 4; j++) pg[j] = acc[i][j];
    }
}

// ---------------------------------------------------------------------------
// Y_diag
// ---------------------------------------------------------------------------
__global__ __launch_bounds__(256) void ydiag_kernel() {
    int bc = blockIdx.x;
    int h = blockIdx.y;
    int sT = blockIdx.z;
    int b = bc / Nc, c = bc % Nc;
    int tid = threadIdx.x;
    int ty = tid >> 4, tx = tid & 15;

    __shared__ float Ms[64][65];
    __shared__ float Hs[64][65];
    __shared__ float sAc[64], zAc[64];

    const float* acumC = g_acum + ((size_t)bc * Hh + h) * Ck;
    if (tid < 64) sAc[tid] = acumC[sT * 64 + tid];
    int rowbase = b * Ll + c * Ck;

    float acc[4][4];
#pragma unroll
    for (int i = 0; i < 4; i++)
#pragma unroll
        for (int j = 0; j < 4; j++) acc[i][j] = 0.f;

    for (int zT = 0; zT <= sT; zT++) {
        if (tid < 64) zAc[tid] = acumC[zT * 64 + tid];
        {
            int zz = tid >> 2;
            int p0 = (tid & 3) * 16;
            int l = rowbase + zT * 64 + zz;
            float d = g_dtv[(size_t)l * Hh + h];
            const float* ph = g_conv + (size_t)l * ConvD + h * Pp + p0;
#pragma unroll
            for (int u = 0; u < 16; u++) Hs[zz][p0 + u] = ph[u] * d;
        }
        __syncthreads();
        {
            int ss4 = (tid & 15) * 4;
            int zz4 = (tid >> 4) * 4;
#pragma unroll
            for (int a = 0; a < 4; a++) {
                int zz = zz4 + a;
                float az = zAc[zz];
                int zg = zT * 64 + zz;
#pragma unroll
                for (int q = 0; q < 4; q++) {
                    int ss = ss4 + q;
                    int sg = sT * 64 + ss;
                    float m = 0.f;
                    if (zg <= sg)
                        m = g_gm[((size_t)bc * Ck + sg) * Ck + zg] * expf(sAc[ss] - az);
                    Ms[zz][ss] = m;
                }
            }
        }
        __syncthreads();
#pragma unroll 4
        for (int zz = 0; zz < 64; zz++) {
            float rm[4], rh[4];
#pragma unroll
            for (int i = 0; i < 4; i++) rm[i] = Ms[zz][ty * 4 + i];
#pragma unroll
            for (int j = 0; j < 4; j++) rh[j] = Hs[zz][tx * 4 + j];
#pragma unroll
            for (int i = 0; i < 4; i++)
#pragma unroll
                for (int j = 0; j < 4; j++) acc[i][j] += rm[i] * rh[j];
        }
        __syncthreads();
    }
#pragma unroll
    for (int i = 0; i < 4; i++) {
        int l = rowbase + sT * 64 + ty * 4 + i;
        float* py = g_y + (size_t)l * Inter + h * Pp + tx * 4;
#pragma unroll
        for (int j = 0; j < 4; j++) py[j] = acc[i][j];
    }
}

// ---------------------------------------------------------------------------
// states
// ---------------------------------------------------------------------------
__global__ __launch_bounds__(256) void states_kernel() {
    int bc = blockIdx.x, h = blockIdx.y;
    int b = bc / Nc, c = bc % Nc;
    int tid = threadIdx.x;
    int ty = tid >> 4, tx = tid & 15;
    __shared__ float Hd[32][65];
    __shared__ float Bsm[32][129];
    const float* acumC = g_acum + ((size_t)bc * Hh + h) * Ck;
    float aLast = acumC[Ck - 1];
    int rowbase = b * Ll + c * Ck;
    float acc[4][8];
#pragma unroll
    for (int i = 0; i < 4; i++)
#pragma unroll
        for (int j = 0; j < 8; j++) acc[i][j] = 0.f;

    for (int l0 = 0; l0 < Ck; l0 += 32) {
        {
            int ll = tid >> 3;
            int p0 = (tid & 7) * 8;
            int l = rowbase + l0 + ll;
            float w = g_dtv[(size_t)l * Hh + h] * expf(aLast - acumC[l0 + ll]);
            const float* ph = g_conv + (size_t)l * ConvD + h * Pp + p0;
#pragma unroll
            for (int u = 0; u < 8; u++) Hd[ll][p0 + u] = ph[u] * w;
        }
        {
            int ll = tid >> 3;
            int n0v = (tid & 7) * 16;
            const float* pb = g_conv + (size_t)(rowbase + l0 + ll) * ConvD + Inter + n0v;
#pragma unroll
            for (int u = 0; u < 16; u++) Bsm[ll][n0v + u] = pb[u];
        }
        __syncthreads();
#pragma unroll 4
        for (int ll = 0; ll < 32; ll++) {
            float rh[4], rb[8];
#pragma unroll
            for (int i = 0; i < 4; i++) rh[i] = Hd[ll][ty * 4 + i];
#pragma unroll
            for (int j = 0; j < 8; j++) rb[j] = Bsm[ll][tx * 8 + j];
#pragma unroll
            for (int i = 0; i < 4; i++)
#pragma unroll
                for (int j = 0; j < 8; j++) acc[i][j] += rh[i] * rb[j];
        }
        __syncthreads();
    }
    float* ps = g_states + ((size_t)bc * Hh + h) * Pp * Nn;
#pragma unroll
    for (int i = 0; i < 4; i++)
#pragma unroll
        for (int j = 0; j < 8; j++)
            ps[(ty * 4 + i) * Nn + tx * 8 + j] = acc[i][j];
}

// ---------------------------------------------------------------------------
// Inter-chunk recurrence
// ---------------------------------------------------------------------------
__global__ void prev_kernel() {
    int idx = blockIdx.x * blockDim.x + threadIdx.x;
    if (idx >= Bb * Hh * Pp * Nn) return;
    int n = idx % Nn;
    int p = (idx / Nn) % Pp;
    int h = (idx / (Nn * Pp)) % Hh;
    int b = idx / (Nn * Pp * Hh);
    float r = 0.f;
    for (int c = 0; c < Nc; c++) {
        size_t off = (((size_t)(b * Nc + c) * Hh + h) * Pp + p) * Nn + n;
        g_prev[off] = r;
        float zl = g_acum[((size_t)(b * Nc + c) * Hh + h) * Ck + (Ck - 1)];
        r = g_states[off] + expf(zl) * r;
    }
}

// ---------------------------------------------------------------------------
// Y_off + combine
// ---------------------------------------------------------------------------
__global__ __launch_bounds__(256) void yoff_kernel(const float* __restrict__ Dv) {
    int bc = blockIdx.x, h = blockIdx.y, lT = blockIdx.z;
    int b = bc / Nc, c = bc % Nc;
    int tid = threadIdx.x;
    int ty = tid >> 4, tx = tid & 15;
    __shared__ float Cs[16][65];
    __shared__ float Ps[16][65];
    __shared__ float lAc[64];
    const float* acumC = g_acum + ((size_t)bc * Hh + h) * Ck;
    if (tid < 64) lAc[tid] = acumC[lT * 64 + tid];
    int rowbase = b * Ll + c * Ck + lT * 64;
    const float* pprev = g_prev + ((size_t)bc * Hh + h) * Pp * Nn;

    float acc[4][4];
#pragma unroll
    for (int i = 0; i < 4; i++)
#pragma unroll
        for (int j = 0; j < 4; j++) acc[i][j] = 0.f;

    int lrow = tid >> 2;
    int lcol = (tid & 3) * 4;
    for (int n0 = 0; n0 < Nn; n0 += 16) {
        const float* pc = g_conv + (size_t)(rowbase + lrow) * ConvD + Inter + Nn + n0 + lcol;
#pragma unroll
        for (int u = 0; u < 4; u++) Cs[lcol + u][lrow] = pc[u];
        const float* pp = pprev + (size_t)lrow * Nn + n0 + lcol;
#pragma unroll
        for (int u = 0; u < 4; u++) Ps[lcol + u][lrow] = pp[u];
        __syncthreads();
#pragma unroll
        for (int kk = 0; kk < 16; kk++) {
            float rc[4], rp[4];
#pragma unroll
            for (int i = 0; i < 4; i++) rc[i] = Cs[kk][ty * 4 + i];
#pragma unroll
            for (int j = 0; j < 4; j++) rp[j] = Ps[kk][tx * 4 + j];
#pragma unroll
            for (int i = 0; i < 4; i++)
#pragma unroll
                for (int j = 0; j < 4; j++) acc[i][j] += rc[i] * rp[j];
        }
        __syncthreads();
    }
    float Dh = Dv[h];
#pragma unroll
    for (int i = 0; i < 4; i++) {
        int ll = ty * 4 + i;
        int l = rowbase + ll;
        float sd = expf(lAc[ll]);
        const float* ph = g_conv + (size_t)l * ConvD + h * Pp;
        float* py = g_y + (size_t)l * Inter + h * Pp;
#pragma unroll
        for (int j = 0; j < 4; j++) {
            int p = tx * 4 + j;
            py[p] = py[p] + acc[i][j] * sd + Dh * ph[p];
        }
    }
}

// ---------------------------------------------------------------------------
// Gated RMSNorm; writes bf16 hi/lo splits directly (fused split_y)
// ---------------------------------------------------------------------------
__global__ __launch_bounds__(256) void norm_kernel(const float* __restrict__ norm_w) {
    int row = blockIdx.x;
    int tid = threadIdx.x;
    const float* pg = g_proj + (size_t)row * ProjD;
    const float* py = g_y + (size_t)row * Inter;
    float f[8];
    float ss = 0.f;
#pragma unroll
    for (int u = 0; u < 8; u++) {
        int i = tid + u * 256;
        float g = pg[i];
        float v = py[i] * siluf(g);
        f[u] = v;
        ss += v * v;
    }
    __shared__ float red[8];
    int lane = tid & 31, wid = tid >> 5;
#pragma unroll
    for (int o = 16; o > 0; o >>= 1) ss += __shfl_xor_sync(0xffffffffu, ss, o);
    if (lane == 0) red[wid] = ss;
    __syncthreads();
    if (tid == 0) {
        float t = 0.f;
#pragma unroll
        for (int i = 0; i < 8; i++) t += red[i];
        red[0] = t;
    }
    __syncthreads();
    float rs = rsqrtf(red[0] / (float)Inter + 1e-6f);
#pragma unroll
    for (int u = 0; u < 8; u++) {
        int i = tid + u * 256;
        float v = f[u] * rs * norm_w[i];
        __nv_bfloat16 h = __float2bfloat16(v);
        size_t o = (size_t)row * Inter + i;
        g_Ah[o] = h;
        g_Al[o] = __float2bfloat16(v - __bfloat162float(h));
    }
}

// ---------------------------------------------------------------------------
// Launch
// ---------------------------------------------------------------------------
extern "C" void kernel_launch(void* const* d_in, const int* in_sizes, int n_in,
                              void* d_out, int out_size) {
    const float* x         = (const float*)d_in[0];
    const float* in_proj_w = (const float*)d_in[1];
    const float* conv_w    = (const float*)d_in[2];
    const float* conv_b    = (const float*)d_in[3];
    const float* dt_bias   = (const float*)d_in[4];
    const float* A_log     = (const float*)d_in[5];
    const float* Dv        = (const float*)d_in[6];
    const float* norm_w    = (const float*)d_in[7];
    const float* out_proj_w= (const float*)d_in[8];
    float* out = (float*)d_out;

    cudaFuncSetAttribute(gemm_in_kernel, cudaFuncAttributeMaxDynamicSharedMemorySize, GEMM_SMEM);
    cudaFuncSetAttribute(gemm_out_kernel, cudaFuncAttributeMaxDynamicSharedMemorySize, GEMM_SMEM);

    // 1) split x and in_proj_w to bf16 hi/lo
    {
        int n = BL * Dm;
        split_x_kernel<<<(n + 255) / 256, 256>>>(x, n);
        n = ProjD * Dm;
        split_w_kernel<<<(n + 255) / 256, 256>>>(in_proj_w, n);
    }
    // 2) in-projection GEMM (mma.sync): [4096,1024] x [4384,1024]^T -> g_proj
    {
        dim3 grid((ProjD + 127) / 128, BL / 128);
        gemm_in_kernel<<<grid, 256, GEMM_SMEM>>>();
    }
    // 3) depthwise causal conv + SiLU
    {
        int total = BL * ConvD;
        conv_silu_kernel<<<(total + 255) / 256, 256>>>(conv_w, conv_b);
    }
    // 4) dt softplus
    {
        int total = BL * Hh;
        dt_kernel<<<(total + 255) / 256, 256>>>(dt_bias);
    }
    // 5) per-chunk cumsum of dt*A
    acum_kernel<<<Bb * Nc * Hh, Ck>>>(A_log);
    // 6) Gm = C B^T per (b,c)
    {
        dim3 grid(Bb * Nc, Ck / 64, Ck / 64);
        gm_kernel<<<grid, 256>>>();
    }
    // 7) intra-chunk Y_diag
    {
        dim3 grid(Bb * Nc, Hh, Ck / 64);
        ydiag_kernel<<<grid, 256>>>();
    }
    // 8) per-chunk final states
    {
        dim3 grid(Bb * Nc, Hh);
        states_kernel<<<grid, 256>>>();
    }
    // 9) inter-chunk recurrence
    {
        int total = Bb * Hh * Pp * Nn;
        prev_kernel<<<(total + 255) / 256, 256>>>();
    }
    // 10) Y_off + D residual + combine
    {
        dim3 grid(Bb * Nc, Hh, Ck / 64);
        yoff_kernel<<<grid, 256>>>(Dv);
    }
    // 11) gated RMSNorm (writes bf16 splits for out-proj)
    norm_kernel<<<BL, 256>>>(norm_w);
    // 12) split out_proj_w
    {
        int n = Dm * Inter;
        split_w_kernel<<<(n + 255) / 256, 256>>>(out_proj_w, n);
    }
    // 13) out-projection GEMM (mma.sync): [4096,2048] x [1024,2048]^T -> out
    {
        dim3 grid(Dm / 128, BL / 128);
        gemm_out_kernel<<<grid, 256, GEMM_SMEM>>>(out);
    }
    (void)in_sizes; (void)n_in; (void)out_size;
}

// round 6
// speedup vs baseline: 1.6695x; 1.0206x over previous
#include <cuda_runtime.h>
#include <cuda_bf16.h>
#include <math.h>
#include <stdint.h>

// ---------------------------------------------------------------------------
// Problem constants (fixed shapes)
// ---------------------------------------------------------------------------
#define Bb     2
#define Ll     2048
#define Dm     1024
#define Hh     32
#define Pp     64
#define Nn     128
#define KCONV  4
#define Ck     256
#define Nc     8          // Ll / Ck
#define Inter  2048
#define ConvD  2304
#define ProjD  4384
#define BL     (Bb * Ll)  // 4096

// ---------------------------------------------------------------------------
// Scratch (device globals; no dynamic allocation allowed)
// ---------------------------------------------------------------------------
__device__ float g_proj[(size_t)BL * ProjD];
__device__ float g_conv[(size_t)BL * ConvD];
__device__ float g_dtv[(size_t)BL * Hh];
__device__ float g_acum[(size_t)Bb * Nc * Hh * Ck];
__device__ float g_gm[(size_t)Bb * Nc * Ck * Ck];
__device__ float g_y[(size_t)BL * Inter];
__device__ float g_states[(size_t)Bb * Nc * Hh * Pp * Nn];
__device__ float g_prev[(size_t)Bb * Nc * Hh * Pp * Nn];

// bf16 split buffers
__device__ __nv_bfloat16 g_Ah[(size_t)BL * Inter];
__device__ __nv_bfloat16 g_Al[(size_t)BL * Inter];
__device__ __nv_bfloat16 g_Bh[(size_t)ProjD * Dm];
__device__ __nv_bfloat16 g_Bl[(size_t)ProjD * Dm];

__device__ __forceinline__ float siluf(float x) { return x / (1.f + expf(-x)); }

// ---------------------------------------------------------------------------
// PTX helpers
// ---------------------------------------------------------------------------
__device__ __forceinline__ unsigned su32(const void* p) {
    return (unsigned)__cvta_generic_to_shared(p);
}

__device__ __forceinline__ void cp16(unsigned dst, const void* src, bool ok) {
    int sz = ok ? 16 : 0;
    asm volatile("cp.async.cg.shared.global [%0], [%1], 16, %2;\n"
                 :: "r"(dst), "l"(src), "r"(sz));
}

__device__ __forceinline__ void ldsm4(unsigned& r0, unsigned& r1, unsigned& r2, unsigned& r3,
                                      unsigned addr) {
    asm volatile("ldmatrix.sync.aligned.m8n8.x4.shared.b16 {%0,%1,%2,%3}, [%4];"
                 : "=r"(r0), "=r"(r1), "=r"(r2), "=r"(r3) : "r"(addr));
}

__device__ __forceinline__ void mma16816(float* c, const unsigned* a, const unsigned* b) {
    asm volatile(
        "mma.sync.aligned.m16n8k16.row.col.f32.bf16.bf16.f32 "
        "{%0,%1,%2,%3}, {%4,%5,%6,%7}, {%8,%9}, {%0,%1,%2,%3};"
        : "+f"(c[0]), "+f"(c[1]), "+f"(c[2]), "+f"(c[3])
        : "r"(a[0]), "r"(a[1]), "r"(a[2]), "r"(a[3]), "r"(b[0]), "r"(b[1]));
}

// ---------------------------------------------------------------------------
// Tensor-core bf16-split GEMM: C[M,N] = A[M,K] * B[N,K]^T
// 3-pass split: C = Ah*Bh + Ah*Bl + Al*Bh (fp32 accum).
// Tile 128x128x64, 256 threads (8 warps: 2(m) x 4(n)), warp tile 64x32.
// ---------------------------------------------------------------------------
#define GEMM_SMEM (2 * 73728)

struct Frags {
    unsigned ah[4][4], al[4][4];
    unsigned bh[4][2], bl[4][2];
};

__device__ __forceinline__ void load_frags(Frags& F, unsigned stg, int ks,
                                           int wm, int wn, int lane) {
    const int rA = lane & 15;
    const int cB = ((lane >> 4) << 4);           // 0 or 16 bytes
    const unsigned colb = (unsigned)(ks * 32 + cB);
#pragma unroll
    for (int mf = 0; mf < 4; mf++) {
        unsigned ra = stg + (wm * 64 + mf * 16 + rA) * 144 + colb;
        ldsm4(F.ah[mf][0], F.ah[mf][1], F.ah[mf][2], F.ah[mf][3], ra);
        ldsm4(F.al[mf][0], F.al[mf][1], F.al[mf][2], F.al[mf][3], ra + 18432);
    }
#pragma unroll
    for (int nf2 = 0; nf2 < 2; nf2++) {
        unsigned rb = stg + 36864 + (wn * 32 + nf2 * 16 + rA) * 144 + colb;
        unsigned t0, t1, t2, t3;
        ldsm4(t0, t1, t2, t3, rb);
        F.bh[nf2 * 2][0] = t0; F.bh[nf2 * 2][1] = t2;
        F.bh[nf2 * 2 + 1][0] = t1; F.bh[nf2 * 2 + 1][1] = t3;
        ldsm4(t0, t1, t2, t3, rb + 18432);
        F.bl[nf2 * 2][0] = t0; F.bl[nf2 * 2][1] = t2;
        F.bl[nf2 * 2 + 1][0] = t1; F.bl[nf2 * 2 + 1][1] = t3;
    }
}

__device__ __forceinline__ void gemm_core(const __nv_bfloat16* __restrict__ Ah,
                                          const __nv_bfloat16* __restrict__ Al,
                                          const __nv_bfloat16* __restrict__ Bh,
                                          const __nv_bfloat16* __restrict__ Bl,
                                          float* __restrict__ C,
                                          int M, int N, int K) {
    extern __shared__ char dyn[];
    const unsigned sbase = su32(dyn);
    const int tid = threadIdx.x;
    const int lane = tid & 31;
    const int warp = tid >> 5;
    const int wm = warp >> 2;   // 0..1
    const int wn = warp & 3;    // 0..3
    const int m0 = blockIdx.y * 128;
    const int n0 = blockIdx.x * 128;
    const int KB = K >> 6;

    float acc[4][4][4];
#pragma unroll
    for (int a = 0; a < 4; a++)
#pragma unroll
        for (int b = 0; b < 4; b++)
#pragma unroll
            for (int c = 0; c < 4; c++) acc[a][b][c] = 0.f;

    auto issue = [&](int kc, int st) {
        unsigned stg = sbase + st * 73728;
#pragma unroll
        for (int i = 0; i < 16; i++) {
            int q = tid + (i << 8);           // 0..4095
            int mat = q >> 10;                // 0:Ah 1:Al 2:Bh 3:Bl
            int r = (q >> 3) & 127;
            int c16 = q & 7;
            const __nv_bfloat16* base = (mat == 0) ? Ah : (mat == 1) ? Al : (mat == 2) ? Bh : Bl;
            int gr = ((mat < 2) ? m0 : n0) + r;
            bool ok = gr < ((mat < 2) ? M : N);
            if (!ok) gr = ((mat < 2) ? M : N) - 1;
            const void* src = base + (size_t)gr * K + (kc << 6) + (c16 << 3);
            unsigned dst = stg + mat * 18432 + r * 144 + (c16 << 4);
            cp16(dst, src, ok);
        }
        asm volatile("cp.async.commit_group;\n");
    };

    issue(0, 0);
    if (KB > 1) issue(1, 1);

    Frags F[2];

    for (int kb = 0; kb < KB; kb++) {
        int st = kb & 1;
        if (kb + 1 < KB) asm volatile("cp.async.wait_group 1;\n");
        else             asm volatile("cp.async.wait_group 0;\n");
        __syncthreads();
        unsigned stg = sbase + st * 73728;

        load_frags(F[0], stg, 0, wm, wn, lane);
#pragma unroll
        for (int ks = 0; ks < 4; ks++) {
            if (ks < 3) load_frags(F[(ks + 1) & 1], stg, ks + 1, wm, wn, lane);
            Frags& f = F[ks & 1];
#pragma unroll
            for (int mf = 0; mf < 4; mf++)
#pragma unroll
                for (int nf = 0; nf < 4; nf++) {
                    mma16816(acc[mf][nf], f.ah[mf], f.bh[nf]);
                    mma16816(acc[mf][nf], f.ah[mf], f.bl[nf]);
                    mma16816(acc[mf][nf], f.al[mf], f.bh[nf]);
                }
        }
        __syncthreads();
        if (kb + 2 < KB) issue(kb + 2, st);
    }

    // epilogue
    int g4 = lane >> 2, t4 = lane & 3;
#pragma unroll
    for (int mf = 0; mf < 4; mf++) {
        int r0 = m0 + wm * 64 + mf * 16 + g4;
#pragma unroll
        for (int nf = 0; nf < 4; nf++) {
            int cg = n0 + wn * 32 + nf * 8 + t4 * 2;
            if (cg < N) {
                float* p0 = C + (size_t)r0 * N + cg;
                p0[0] = acc[mf][nf][0];
                p0[1] = acc[mf][nf][1];
                float* p1 = p0 + (size_t)8 * N;
                p1[0] = acc[mf][nf][2];
                p1[1] = acc[mf][nf][3];
            }
        }
    }
}

__global__ __launch_bounds__(256) void gemm_in_kernel() {
    gemm_core(g_Ah, g_Al, g_Bh, g_Bl, g_proj, BL, ProjD, Dm);
}

__global__ __launch_bounds__(256) void gemm_out_kernel(float* __restrict__ out) {
    gemm_core(g_Ah, g_Al, g_Bh, g_Bl, out, BL, Dm, Inter);
}

// ---------------------------------------------------------------------------
// bf16 split conversions
// ---------------------------------------------------------------------------
__global__ void split_x_kernel(const float* __restrict__ in, int n) {
    int i = blockIdx.x * blockDim.x + threadIdx.x;
    if (i >= n) return;
    float v = in[i];
    __nv_bfloat16 h = __float2bfloat16(v);
    g_Ah[i] = h;
    g_Al[i] = __float2bfloat16(v - __bfloat162float(h));
}

__global__ void split_w_kernel(const float* __restrict__ in, int n) {
    int i = blockIdx.x * blockDim.x + threadIdx.x;
    if (i >= n) return;
    float v = in[i];
    __nv_bfloat16 h = __float2bfloat16(v);
    g_Bh[i] = h;
    g_Bl[i] = __float2bfloat16(v - __bfloat162float(h));
}

// ---------------------------------------------------------------------------
// Depthwise causal conv1d (K=4) + bias + SiLU — sliding-window version.
// Each thread owns one (b, channel) and walks 64 sequence positions,
// keeping the 4-tap window in registers (1 LDG per output instead of 4).
// grid: (ConvD/256, Ll/64, Bb), 256 threads.
// ---------------------------------------------------------------------------
__global__ __launch_bounds__(256) void conv_silu_kernel(const float* __restrict__ cw,
                                                        const float* __restrict__ cb) {
    int ch = blockIdx.x * 256 + threadIdx.x;
    int l0 = blockIdx.y * 64;
    int b  = blockIdx.z;
    const float* col = g_proj + (size_t)b * Ll * ProjD + Inter + ch;
    float w0 = cw[ch * KCONV + 0];
    float w1 = cw[ch * KCONV + 1];
    float w2 = cw[ch * KCONV + 2];
    float w3 = cw[ch * KCONV + 3];
    float bias = cb[ch];
    float xm3 = (l0 >= 3) ? col[(size_t)(l0 - 3) * ProjD] : 0.f;
    float xm2 = (l0 >= 2) ? col[(size_t)(l0 - 2) * ProjD] : 0.f;
    float xm1 = (l0 >= 1) ? col[(size_t)(l0 - 1) * ProjD] : 0.f;
    float* outp = g_conv + (size_t)(b * Ll + l0) * ConvD + ch;
#pragma unroll 4
    for (int i = 0; i < 64; i++) {
        float x0 = col[(size_t)(l0 + i) * ProjD];
        float acc = bias + w0 * xm3 + w1 * xm2 + w2 * xm1 + w3 * x0;
        outp[(size_t)i * ConvD] = siluf(acc);
        xm3 = xm2; xm2 = xm1; xm1 = x0;
    }
}

// ---------------------------------------------------------------------------
// Per-chunk inclusive cumsum of dt * A, with fused softplus(dt + bias).
// block = one (b,c,h), 256 threads. Also writes g_dtv.
// ---------------------------------------------------------------------------
__global__ void acum_kernel(const float* __restrict__ A_log,
                            const float* __restrict__ dt_bias) {
    int blk = blockIdx.x;
    int h = blk % Hh;
    int bc = blk / Hh;
    int b = bc / Nc, c = bc % Nc;
    int t = threadIdx.x;
    float A = -expf(A_log[h]);
    int bl = b * Ll + c * Ck + t;
    float raw = g_proj[(size_t)bl * ProjD + Inter + ConvD + h] + dt_bias[h];
    float dt = (raw > 20.f) ? raw : log1pf(expf(raw));
    g_dtv[(size_t)bl * Hh + h] = dt;
    float v = dt * A;
    __shared__ float s[Ck];
    s[t] = v;
    __syncthreads();
    for (int off = 1; off < Ck; off <<= 1) {
        float x = (t >= off) ? s[t - off] : 0.f;
        __syncthreads();
        s[t] += x;
        __syncthreads();
    }
    g_acum[(size_t)blk * Ck + t] = s[t];
}

// ---------------------------------------------------------------------------
// Gm[s,z] = sum_n C[s,n] * B[z,n] per (b,c), lower triangle tiles
// ---------------------------------------------------------------------------
__global__ __launch_bounds__(256) void gm_kernel() {
    int bc = blockIdx.x;
    int sT = blockIdx.y, zT = blockIdx.z;
    if (zT > sT) return;
    int b = bc / Nc, c = bc % Nc;
    int rowbase = b * Ll + c * Ck;
    __shared__ float Cs[16][65];
    __shared__ float Bs[16][65];
    int tid = threadIdx.x;
    int ty = tid >> 4, tx = tid & 15;
    float acc[4][4];
#pragma unroll
    for (int i = 0; i < 4; i++)
#pragma unroll
        for (int j = 0; j < 4; j++) acc[i][j] = 0.f;

    int lrow = tid >> 2;
    int lcol = (tid & 3) * 4;

    for (int n0 = 0; n0 < Nn; n0 += 16) {
        const float* pc = g_conv + (size_t)(rowbase + sT * 64 + lrow) * ConvD + Inter + Nn + n0 + lcol;
        const float* pb = g_conv + (size_t)(rowbase + zT * 64 + lrow) * ConvD + Inter + n0 + lcol;
#pragma unroll
        for (int u = 0; u < 4; u++) Cs[lcol + u][lrow] = pc[u];
#pragma unroll
        for (int u = 0; u < 4; u++) Bs[lcol + u][lrow] = pb[u];
        __syncthreads();
#pragma unroll
        for (int kk = 0; kk < 16; kk++) {
            float rc[4], rb[4];
#pragma unroll
            for (int i = 0; i < 4; i++) rc[i] = Cs[kk][ty * 4 + i];
#pragma unroll
            for (int j = 0; j < 4; j++) rb[j] = Bs[kk][tx * 4 + j];
#pragma unroll
            for (int i = 0; i < 4; i++)
#pragma unroll
                for (int j = 0; j < 4; j++) acc[i][j] += rc[i] * rb[j];
        }
        __syncthreads();
    }
#pragma unroll
    for (int i = 0; i < 4; i++) {
        int sg = sT * 64 + ty * 4 + i;
        float* pg = g_gm + ((size_t)bc * Ck + sg) * Ck + zT * 64 + tx * 4;
#pragma unroll
        for (int j = 0; j < 4; j++) pg[j] = acc[i][j];
    }
}

// ---------------------------------------------------------------------------
// Y_diag — Gm reads now coalesced (lanes vary zg, half-warp reads one row run)
// ---------------------------------------------------------------------------
__global__ __launch_bounds__(256) void ydiag_kernel() {
    int bc = blockIdx.x;
    int h = blockIdx.y;
    int sT = blockIdx.z;
    int b = bc / Nc, c = bc % Nc;
    int tid = threadIdx.x;
    int ty = tid >> 4, tx = tid & 15;

    __shared__ float Ms[64][65];
    __shared__ float Hs[64][65];
    __shared__ float sAc[64], zAc[64];

    const float* acumC = g_acum + ((size_t)bc * Hh + h) * Ck;
    if (tid < 64) sAc[tid] = acumC[sT * 64 + tid];
    int rowbase = b * Ll + c * Ck;

    float acc[4][4];
#pragma unroll
    for (int i = 0; i < 4; i++)
#pragma unroll
        for (int j = 0; j < 4; j++) acc[i][j] = 0.f;

    for (int zT = 0; zT <= sT; zT++) {
        if (tid < 64) zAc[tid] = acumC[zT * 64 + tid];
        {
            int zz = tid >> 2;
            int p0 = (tid & 3) * 16;
            int l = rowbase + zT * 64 + zz;
            float d = g_dtv[(size_t)l * Hh + h];
            const float* ph = g_conv + (size_t)l * ConvD + h * Pp + p0;
#pragma unroll
            for (int u = 0; u < 16; u++) Hs[zz][p0 + u] = ph[u] * d;
        }
        __syncthreads();
        {
            // lanes vary zg (coalesced g_gm row reads)
            int zz4 = (tid & 15) * 4;
            int ss4 = (tid >> 4) * 4;
            bool full = (zT < sT);
#pragma unroll
            for (int a = 0; a < 4; a++) {
                int ss = ss4 + a;
                int sg = sT * 64 + ss;
                float as = sAc[ss];
                const float* grow = g_gm + ((size_t)bc * Ck + sg) * Ck + zT * 64 + zz4;
#pragma unroll
                for (int q = 0; q < 4; q++) {
                    int zz = zz4 + q;
                    float m = 0.f;
                    if (full || (zT * 64 + zz) <= sg)
                        m = grow[q] * expf(as - zAc[zz]);
                    Ms[zz][ss] = m;
                }
            }
        }
        __syncthreads();
#pragma unroll 4
        for (int zz = 0; zz < 64; zz++) {
            float rm[4], rh[4];
#pragma unroll
            for (int i = 0; i < 4; i++) rm[i] = Ms[zz][ty * 4 + i];
#pragma unroll
            for (int j = 0; j < 4; j++) rh[j] = Hs[zz][tx * 4 + j];
#pragma unroll
            for (int i = 0; i < 4; i++)
#pragma unroll
                for (int j = 0; j < 4; j++) acc[i][j] += rm[i] * rh[j];
        }
        __syncthreads();
    }
#pragma unroll
    for (int i = 0; i < 4; i++) {
        int l = rowbase + sT * 64 + ty * 4 + i;
        float* py = g_y + (size_t)l * Inter + h * Pp + tx * 4;
#pragma unroll
        for (int j = 0; j < 4; j++) py[j] = acc[i][j];
    }
}

// ---------------------------------------------------------------------------
// states
// ---------------------------------------------------------------------------
__global__ __launch_bounds__(256) void states_kernel() {
    int bc = blockIdx.x, h = blockIdx.y;
    int b = bc / Nc, c = bc % Nc;
    int tid = threadIdx.x;
    int ty = tid >> 4, tx = tid & 15;
    __shared__ float Hd[32][65];
    __shared__ float Bsm[32][129];
    const float* acumC = g_acum + ((size_t)bc * Hh + h) * Ck;
    float aLast = acumC[Ck - 1];
    int rowbase = b * Ll + c * Ck;
    float acc[4][8];
#pragma unroll
    for (int i = 0; i < 4; i++)
#pragma unroll
        for (int j = 0; j < 8; j++) acc[i][j] = 0.f;

    for (int l0 = 0; l0 < Ck; l0 += 32) {
        {
            int ll = tid >> 3;
            int p0 = (tid & 7) * 8;
            int l = rowbase + l0 + ll;
            float w = g_dtv[(size_t)l * Hh + h] * expf(aLast - acumC[l0 + ll]);
            const float* ph = g_conv + (size_t)l * ConvD + h * Pp + p0;
#pragma unroll
            for (int u = 0; u < 8; u++) Hd[ll][p0 + u] = ph[u] * w;
        }
        {
            int ll = tid >> 3;
            int n0v = (tid & 7) * 16;
            const float* pb = g_conv + (size_t)(rowbase + l0 + ll) * ConvD + Inter + n0v;
#pragma unroll
            for (int u = 0; u < 16; u++) Bsm[ll][n0v + u] = pb[u];
        }
        __syncthreads();
#pragma unroll 4
        for (int ll = 0; ll < 32; ll++) {
            float rh[4], rb[8];
#pragma unroll
            for (int i = 0; i < 4; i++) rh[i] = Hd[ll][ty * 4 + i];
#pragma unroll
            for (int j = 0; j < 8; j++) rb[j] = Bsm[ll][tx * 8 + j];
#pragma unroll
            for (int i = 0; i < 4; i++)
#pragma unroll
                for (int j = 0; j < 8; j++) acc[i][j] += rh[i] * rb[j];
        }
        __syncthreads();
    }
    float* ps = g_states + ((size_t)bc * Hh + h) * Pp * Nn;
#pragma unroll
    for (int i = 0; i < 4; i++)
#pragma unroll
        for (int j = 0; j < 8; j++)
            ps[(ty * 4 + i) * Nn + tx * 8 + j] = acc[i][j];
}

// ---------------------------------------------------------------------------
// Inter-chunk recurrence
// ---------------------------------------------------------------------------
__global__ void prev_kernel() {
    int idx = blockIdx.x * blockDim.x + threadIdx.x;
    if (idx >= Bb * Hh * Pp * Nn) return;
    int n = idx % Nn;
    int p = (idx / Nn) % Pp;
    int h = (idx / (Nn * Pp)) % Hh;
    int b = idx / (Nn * Pp * Hh);
    float r = 0.f;
    for (int c = 0; c < Nc; c++) {
        size_t off = (((size_t)(b * Nc + c) * Hh + h) * Pp + p) * Nn + n;
        g_prev[off] = r;
        float zl = g_acum[((size_t)(b * Nc + c) * Hh + h) * Ck + (Ck - 1)];
        r = g_states[off] + expf(zl) * r;
    }
}

// ---------------------------------------------------------------------------
// Y_off + combine
// ---------------------------------------------------------------------------
__global__ __launch_bounds__(256) void yoff_kernel(const float* __restrict__ Dv) {
    int bc = blockIdx.x, h = blockIdx.y, lT = blockIdx.z;
    int b = bc / Nc, c = bc % Nc;
    int tid = threadIdx.x;
    int ty = tid >> 4, tx = tid & 15;
    __shared__ float Cs[16][65];
    __shared__ float Ps[16][65];
    __shared__ float lAc[64];
    const float* acumC = g_acum + ((size_t)bc * Hh + h) * Ck;
    if (tid < 64) lAc[tid] = acumC[lT * 64 + tid];
    int rowbase = b * Ll + c * Ck + lT * 64;
    const float* pprev = g_prev + ((size_t)bc * Hh + h) * Pp * Nn;

    float acc[4][4];
#pragma unroll
    for (int i = 0; i < 4; i++)
#pragma unroll
        for (int j = 0; j < 4; j++) acc[i][j] = 0.f;

    int lrow = tid >> 2;
    int lcol = (tid & 3) * 4;
    for (int n0 = 0; n0 < Nn; n0 += 16) {
        const float* pc = g_conv + (size_t)(rowbase + lrow) * ConvD + Inter + Nn + n0 + lcol;
#pragma unroll
        for (int u = 0; u < 4; u++) Cs[lcol + u][lrow] = pc[u];
        const float* pp = pprev + (size_t)lrow * Nn + n0 + lcol;
#pragma unroll
        for (int u = 0; u < 4; u++) Ps[lcol + u][lrow] = pp[u];
        __syncthreads();
#pragma unroll
        for (int kk = 0; kk < 16; kk++) {
            float rc[4], rp[4];
#pragma unroll
            for (int i = 0; i < 4; i++) rc[i] = Cs[kk][ty * 4 + i];
#pragma unroll
            for (int j = 0; j < 4; j++) rp[j] = Ps[kk][tx * 4 + j];
#pragma unroll
            for (int i = 0; i < 4; i++)
#pragma unroll
                for (int j = 0; j < 4; j++) acc[i][j] += rc[i] * rp[j];
        }
        __syncthreads();
    }
    float Dh = Dv[h];
#pragma unroll
    for (int i = 0; i < 4; i++) {
        int ll = ty * 4 + i;
        int l = rowbase + ll;
        float sd = expf(lAc[ll]);
        const float* ph = g_conv + (size_t)l * ConvD + h * Pp;
        float* py = g_y + (size_t)l * Inter + h * Pp;
#pragma unroll
        for (int j = 0; j < 4; j++) {
            int p = tx * 4 + j;
            py[p] = py[p] + acc[i][j] * sd + Dh * ph[p];
        }
    }
}

// ---------------------------------------------------------------------------
// Gated RMSNorm; writes bf16 hi/lo splits directly (fused split_y)
// ---------------------------------------------------------------------------
__global__ __launch_bounds__(256) void norm_kernel(const float* __restrict__ norm_w) {
    int row = blockIdx.x;
    int tid = threadIdx.x;
    const float* pg = g_proj + (size_t)row * ProjD;
    const float* py = g_y + (size_t)row * Inter;
    float f[8];
    float ss = 0.f;
#pragma unroll
    for (int u = 0; u < 8; u++) {
        int i = tid + u * 256;
        float g = pg[i];
        float v = py[i] * siluf(g);
        f[u] = v;
        ss += v * v;
    }
    __shared__ float red[8];
    int lane = tid & 31, wid = tid >> 5;
#pragma unroll
    for (int o = 16; o > 0; o >>= 1) ss += __shfl_xor_sync(0xffffffffu, ss, o);
    if (lane == 0) red[wid] = ss;
    __syncthreads();
    if (tid == 0) {
        float t = 0.f;
#pragma unroll
        for (int i = 0; i < 8; i++) t += red[i];
        red[0] = t;
    }
    __syncthreads();
    float rs = rsqrtf(red[0] / (float)Inter + 1e-6f);
#pragma unroll
    for (int u = 0; u < 8; u++) {
        int i = tid + u * 256;
        float v = f[u] * rs * norm_w[i];
        __nv_bfloat16 h = __float2bfloat16(v);
        size_t o = (size_t)row * Inter + i;
        g_Ah[o] = h;
        g_Al[o] = __float2bfloat16(v - __bfloat162float(h));
    }
}

// ---------------------------------------------------------------------------
// Launch
// ---------------------------------------------------------------------------
extern "C" void kernel_launch(void* const* d_in, const int* in_sizes, int n_in,
                              void* d_out, int out_size) {
    const float* x         = (const float*)d_in[0];
    const float* in_proj_w = (const float*)d_in[1];
    const float* conv_w    = (const float*)d_in[2];
    const float* conv_b    = (const float*)d_in[3];
    const float* dt_bias   = (const float*)d_in[4];
    const float* A_log     = (const float*)d_in[5];
    const float* Dv        = (const float*)d_in[6];
    const float* norm_w    = (const float*)d_in[7];
    const float* out_proj_w= (const float*)d_in[8];
    float* out = (float*)d_out;

    cudaFuncSetAttribute(gemm_in_kernel, cudaFuncAttributeMaxDynamicSharedMemorySize, GEMM_SMEM);
    cudaFuncSetAttribute(gemm_out_kernel, cudaFuncAttributeMaxDynamicSharedMemorySize, GEMM_SMEM);

    // 1) split x and in_proj_w to bf16 hi/lo
    {
        int n = BL * Dm;
        split_x_kernel<<<(n + 255) / 256, 256>>>(x, n);
        n = ProjD * Dm;
        split_w_kernel<<<(n + 255) / 256, 256>>>(in_proj_w, n);
    }
    // 2) in-projection GEMM (mma.sync): [4096,1024] x [4384,1024]^T -> g_proj
    {
        dim3 grid((ProjD + 127) / 128, BL / 128);
        gemm_in_kernel<<<grid, 256, GEMM_SMEM>>>();
    }
    // 3) depthwise causal conv + SiLU (sliding window)
    {
        dim3 grid(ConvD / 256, Ll / 64, Bb);
        conv_silu_kernel<<<grid, 256>>>(conv_w, conv_b);
    }
    // 4) per-chunk cumsum of dt*A (fused softplus)
    acum_kernel<<<Bb * Nc * Hh, Ck>>>(A_log, dt_bias);
    // 5) Gm = C B^T per (b,c)
    {
        dim3 grid(Bb * Nc, Ck / 64, Ck / 64);
        gm_kernel<<<grid, 256>>>();
    }
    // 6) intra-chunk Y_diag
    {
        dim3 grid(Bb * Nc, Hh, Ck / 64);
        ydiag_kernel<<<grid, 256>>>();
    }
    // 7) per-chunk final states
    {
        dim3 grid(Bb * Nc, Hh);
        states_kernel<<<grid, 256>>>();
    }
    // 8) inter-chunk recurrence
    {
        int total = Bb * Hh * Pp * Nn;
        prev_kernel<<<(total + 255) / 256, 256>>>();
    }
    // 9) Y_off + D residual + combine
    {
        dim3 grid(Bb * Nc, Hh, Ck / 64);
        yoff_kernel<<<grid, 256>>>(Dv);
    }
    // 10) gated RMSNorm (writes bf16 splits for out-proj)
    norm_kernel<<<BL, 256>>>(norm_w);
    // 11) split out_proj_w
    {
        int n = Dm * Inter;
        split_w_kernel<<<(n + 255) / 256, 256>>>(out_proj_w, n);
    }
    // 12) out-projection GEMM (mma.sync): [4096,2048] x [1024,2048]^T -> out
    {
        dim3 grid(Dm / 128, BL / 128);
        gemm_out_kernel<<<grid, 256, GEMM_SMEM>>>(out);
    }
    (void)in_sizes; (void)n_in; (void)out_size;
}